// round 10
// baseline (speedup 1.0000x reference)
#include <cuda_runtime.h>
#include <cuda_fp16.h>
#include <math.h>
#include <stdint.h>

// Problem dims (fixed by the dataset)
#define Bb   16
#define Nn   4096
#define Mm   1024
#define IDim 768
#define HDim 512
#define ODim 256
#define ROWS_IMG (Bb*Mm)   // 16384
#define ROWS_PT  (Bb*Nn)   // 65536

// ---------------- scratch (device globals; no allocation allowed) -------------
__device__ __align__(16) __half g_xln[ROWS_IMG * IDim];          // LN img tokens (fp16, permuted)
__device__ __align__(16) __half g_hbuf[ROWS_PT * 2 * HDim];      // hidden (fp16, permuted)
__device__ __align__(16) float g_imgfeat[ROWS_IMG * ODim];       // image MLP out (fp32 plain)
__device__ __align__(16) __half g_finln[ROWS_PT * (2 * ODim)];   // fin̂ (fp16, permuted)
__device__ __align__(16) float g_gate[ROWS_PT * ODim];           // gate pre-sigmoid (fp32)
__device__ int   g_knn_idx[ROWS_PT * 3];
__device__ float g_knn_w[ROWS_PT * 3];
// transposed (LN-folded) weights: [N,K] K-major, fp16, permuted
__device__ __align__(16) __half g_wt_ip1[HDim * IDim];
__device__ __align__(16) __half g_wt_gd1[(2 * HDim) * HDim];     // fused gate|delta layer-1
__device__ __align__(16) __half g_wt_ip2[ODim * HDim];
__device__ __align__(16) __half g_wt_g2[ODim * HDim];
__device__ __align__(16) __half g_wt_d2[ODim * HDim];
__device__ float g_bp_ip[HDim];
__device__ float g_bp_gd[2 * HDim];                              // fused gate|delta bias

// ---------------- helpers ------------------------------------------------------
// 32-wide k permutation: places a thread's mma fragments for BOTH 16-k steps of
// a 32-k tile into one contiguous 16B chunk (chunk index = (k>>1)&3):
//   pos = ((k>>1)&3)<<3 | ((k>>4)&1)<<2 | ((k>>3)&1)<<1 | (k&1)
// uint4 loaded from chunk i4: .x=(ks0,pair i4) .y=(ks0,pair i4+4)
//                             .z=(ks1,pair i4) .w=(ks1,pair i4+4)
__device__ __host__ __forceinline__ int permk(int k) {
    return (k & ~31) | (((k >> 1) & 3) << 3) | (((k >> 4) & 1) << 2)
         | (((k >> 3) & 1) << 1) | (k & 1);
}
__device__ __forceinline__ float gelu_f(float x) {
    return 0.5f * x * (1.0f + erff(x * 0.70710678118654752f));
}
__device__ __forceinline__ float sigmoid_f(float x) {
    return 1.0f / (1.0f + __expf(-x));
}
__device__ __forceinline__ float2 block_reduce2(float s, float ss) {
    __shared__ float sh[64];
    int lane = threadIdx.x & 31, w = threadIdx.x >> 5;
#pragma unroll
    for (int o = 16; o; o >>= 1) {
        s  += __shfl_down_sync(0xffffffffu, s,  o);
        ss += __shfl_down_sync(0xffffffffu, ss, o);
    }
    if (lane == 0) { sh[w] = s; sh[32 + w] = ss; }
    __syncthreads();
    int nw = (blockDim.x + 31) >> 5;
    if (w == 0) {
        s  = (lane < nw) ? sh[lane]      : 0.0f;
        ss = (lane < nw) ? sh[32 + lane] : 0.0f;
#pragma unroll
        for (int o = 16; o; o >>= 1) {
            s  += __shfl_down_sync(0xffffffffu, s,  o);
            ss += __shfl_down_sync(0xffffffffu, ss, o);
        }
        if (lane == 0) { sh[0] = s; sh[32] = ss; }
    }
    __syncthreads();
    return make_float2(sh[0], sh[32]);
}

// ---------------- K0a: elementwise LN-gain fold + transpose (fp16, permuted) ----
__global__ void fold_w1(const float* __restrict__ W, const float* __restrict__ gain,
                        __half* __restrict__ Wt, int Kd, int Nc) {
    int idx = blockIdx.x * blockDim.x + threadIdx.x;
    if (idx >= Kd * Nc) return;
    int k = idx / Nc, n = idx % Nc;
    Wt[(size_t)n * Kd + permk(k)] = __float2half_rn(gain[k] * W[idx]);
}
// ---------------- K0b: bias fold: b1p[n] = b1[n] + sum_k bln[k]*W[k,n] -----------
__global__ void fold_b1(const float* __restrict__ W, const float* __restrict__ bln,
                        const float* __restrict__ b1, float* __restrict__ b1p,
                        int Kd, int Nc) {
    __shared__ float sh[256];
    int nl = threadIdx.x & 63, ks = threadIdx.x >> 6;
    int n = blockIdx.x * 64 + nl;
    float acc = 0.0f;
    for (int k = ks; k < Kd; k += 4)
        acc += bln[k] * W[(size_t)k * Nc + n];
    sh[threadIdx.x] = acc;
    __syncthreads();
    if (ks == 0)
        b1p[n] = b1[n] + sh[nl] + sh[64 + nl] + sh[128 + nl] + sh[192 + nl];
}
// ---------------- K0c: plain transpose (fp16, permuted) -------------------------
__global__ void transpose_k(const float* __restrict__ W, __half* __restrict__ Wt,
                            int Kd, int Nc) {
    int idx = blockIdx.x * blockDim.x + threadIdx.x;
    if (idx >= Kd * Nc) return;
    int k = idx / Nc, n = idx % Nc;
    Wt[(size_t)n * Kd + permk(k)] = __float2half_rn(W[idx]);
}

// ---------------- K1: LN (normalize only), fp16 permuted store ------------------
__global__ void ln_img_kernel(const float* __restrict__ x, __half* __restrict__ y) {
    int row = blockIdx.x, tid = threadIdx.x;
    const float* xr = x + (size_t)row * IDim;
    float v0 = xr[tid], v1 = xr[tid + 256], v2 = xr[tid + 512];
    float s = v0 + v1 + v2;
    float ss = v0 * v0 + v1 * v1 + v2 * v2;
    float2 r = block_reduce2(s, ss);
    float mean = r.x * (1.0f / 768.0f);
    float var  = fmaxf(r.y * (1.0f / 768.0f) - mean * mean, 0.0f);
    float rstd = rsqrtf(var + 1e-5f);
    __half* yr = y + (size_t)row * IDim;
    yr[permk(tid)]       = __float2half_rn((v0 - mean) * rstd);
    yr[permk(tid + 256)] = __float2half_rn((v1 - mean) * rstd);
    yr[permk(tid + 512)] = __float2half_rn((v2 - mean) * rstd);
}

// ---------------- K2: fp16 m16n8k16 mma.sync GEMM -------------------------------
// C[R,Nc] = A[R,Kd] @ Bt[Nc,Kd]^T; A row stride lda. 128x128 tile, KTILE=32,
// 4-stage cp.async, XOR-swizzled 64B rows, LDS.128 combined-kstep fragments.
// ACT: 0 fp32 out, 1 gelu -> fp16 permuted out (hbuf), 2 final combine fp32 out.
#define KTILE   32
#define ROWB    64                           // bytes/row: 64 data, no pad (XOR swizzle)
#define TILE_B  (128 * ROWB)                 // 8192 bytes
#define STAGE_B (2 * TILE_B)                 // 16384
#define STAGES  4
#define SM_TOTAL (STAGES * STAGE_B)          // 65536 -> 2 CTAs/SM

#define CPA_COMMIT() asm volatile("cp.async.commit_group;" ::: "memory")
#define CPA_WAIT2()  asm volatile("cp.async.wait_group 2;" ::: "memory")

__device__ __forceinline__ uint32_t smem_u32(const void* p) {
    uint32_t a;
    asm("{ .reg .u64 t; cvta.to.shared.u64 t, %1; cvt.u32.u64 %0, t; }" : "=r"(a) : "l"(p));
    return a;
}

// one 128x32(fp16) tile: 128 rows x 64B = 512 x 16B chunks, 2 per thread.
// smem chunk column swizzled: c' = c ^ (r & 3)  (conflict-free store + load)
__device__ __forceinline__ void load_tile(uint32_t sbase, const __half* gbase, int ld) {
    int t = threadIdx.x;
#pragma unroll
    for (int i = 0; i < 2; i++) {
        int idx = t + i * 256;
        int r = idx >> 2, c = idx & 3;
        uint32_t so = sbase + (uint32_t)(r * ROWB + 16 * (c ^ (r & 3)));
        const __half* gp = gbase + (size_t)r * ld + c * 8;
        asm volatile("cp.async.cg.shared.global [%0], [%1], 16;" :: "r"(so), "l"(gp));
    }
}

__device__ __forceinline__ void mma_f16(float* d, uint32_t a0, uint32_t a1, uint32_t a2,
                                        uint32_t a3, uint32_t b0, uint32_t b1) {
    asm volatile(
        "mma.sync.aligned.m16n8k16.row.col.f32.f16.f16.f32 "
        "{%0,%1,%2,%3}, {%4,%5,%6,%7}, {%8,%9}, {%0,%1,%2,%3};"
        : "+f"(d[0]), "+f"(d[1]), "+f"(d[2]), "+f"(d[3])
        : "r"(a0), "r"(a1), "r"(a2), "r"(a3), "r"(b0), "r"(b1));
}

template <int ACT>
__global__ __launch_bounds__(256, 2)
void mma_gemm(const __half* __restrict__ A, int lda, const __half* __restrict__ Bt,
              const float* __restrict__ bias, void* __restrict__ Cv,
              int Kd, int Nc,
              const float* __restrict__ gbuf, const float* __restrict__ ptb,
              const int* __restrict__ pvm) {
    extern __shared__ char smem[];
    uint32_t sb = smem_u32(smem);
    int tid = threadIdx.x, wid = tid >> 5, lane = tid & 31;
    int wm = wid & 1, wn = wid >> 1;              // 2x4 warp grid, warp tile 64x32
    int g = lane >> 2, i4 = lane & 3;
    int row0 = blockIdx.y * 128, col0 = blockIdx.x * 128;

    const int NK = Kd / KTILE;
    const __half* Ag = A  + (size_t)row0 * lda;
    const __half* Bg = Bt + (size_t)col0 * Kd;

    // all 12 fragment loads of this thread share one swizzled chunk offset
    const int sc = 16 * (i4 ^ (g & 3));
    const int a_base = (wm * 64 + g) * ROWB + sc;
    const int b_base = (wn * 32 + g) * ROWB + sc;

    // prologue: stages 0,1,2
#pragma unroll
    for (int p = 0; p < 3; p++) {
        load_tile(sb + p * STAGE_B,          Ag + p * KTILE, lda);
        load_tile(sb + p * STAGE_B + TILE_B, Bg + p * KTILE, Kd);
        CPA_COMMIT();
    }

    float acc[4][4][4];
#pragma unroll
    for (int mf = 0; mf < 4; mf++)
#pragma unroll
        for (int nf = 0; nf < 4; nf++)
#pragma unroll
            for (int e = 0; e < 4; e++) acc[mf][nf][e] = 0.0f;

    for (int kt = 0; kt < NK; kt++) {
        CPA_WAIT2();                 // oldest outstanding group (tile kt) resident
        __syncthreads();
        if (kt + 3 < NK) {
            int st = (kt + 3) % STAGES;
            load_tile(sb + st * STAGE_B,          Ag + (size_t)(kt + 3) * KTILE, lda);
            load_tile(sb + st * STAGE_B + TILE_B, Bg + (size_t)(kt + 3) * KTILE, Kd);
        }
        CPA_COMMIT();

        int s = kt % STAGES;
        const char* As = smem + s * STAGE_B + a_base;
        const char* Bs = smem + s * STAGE_B + TILE_B + b_base;

        // batched fragment loads: 12 x LDS.128, both k-steps at once
        uint4 af[8], bq[4];
#pragma unroll
        for (int mf = 0; mf < 4; mf++) {
            af[2 * mf]     = *(const uint4*)(As + mf * (16 * ROWB));
            af[2 * mf + 1] = *(const uint4*)(As + mf * (16 * ROWB) + 8 * ROWB);
        }
#pragma unroll
        for (int nf = 0; nf < 4; nf++)
            bq[nf] = *(const uint4*)(Bs + nf * (8 * ROWB));

#pragma unroll
        for (int mf = 0; mf < 4; mf++)
#pragma unroll
            for (int nf = 0; nf < 4; nf++) {
                mma_f16(acc[mf][nf],
                        af[2 * mf].x, af[2 * mf + 1].x, af[2 * mf].y, af[2 * mf + 1].y,
                        bq[nf].x, bq[nf].y);
                mma_f16(acc[mf][nf],
                        af[2 * mf].z, af[2 * mf + 1].z, af[2 * mf].w, af[2 * mf + 1].w,
                        bq[nf].z, bq[nf].w);
            }
    }

    // epilogue
#pragma unroll
    for (int mf = 0; mf < 4; mf++) {
        int r_lo = row0 + wm * 64 + mf * 16 + g;
#pragma unroll
        for (int nf = 0; nf < 4; nf++) {
            int col = col0 + wn * 32 + nf * 8 + i4 * 2;
            float b0 = bias[col], b1 = bias[col + 1];
#pragma unroll
            for (int h = 0; h < 2; h++) {
                int row = r_lo + h * 8;
                float v0 = acc[mf][nf][h * 2 + 0] + b0;
                float v1 = acc[mf][nf][h * 2 + 1] + b1;
                if (ACT == 1) {
                    // gelu -> fp16 permuted store (hbuf is next GEMM's A)
                    __half2 o;
                    o.x = __float2half_rn(gelu_f(v0));
                    o.y = __float2half_rn(gelu_f(v1));
                    __half* C = (__half*)Cv;
                    *(__half2*)(C + (size_t)row * Nc + permk(col)) = o;
                } else {
                    float* C = (float*)Cv;
                    size_t off = (size_t)row * Nc + col;
                    if (ACT == 2) {
                        float2 g4 = *(const float2*)(gbuf + off);
                        float2 p4 = *(const float2*)(ptb + off);
                        float m = pvm[row] ? 1.0f : 0.0f;
                        v0 = (p4.x + sigmoid_f(g4.x) * v0) * m;
                        v1 = (p4.y + sigmoid_f(g4.y) * v1) * m;
                    }
                    *(float2*)(C + off) = make_float2(v0, v1);
                }
            }
        }
    }
}

// ---------------- K3: kNN top-3 + inverse-distance weights ----------------------
__global__ __launch_bounds__(256)
void knn_kernel(const float* __restrict__ pc, const float* __restrict__ ic,
                const int* __restrict__ imask,
                int* __restrict__ knn_idx, float* __restrict__ knn_w) {
    __shared__ float4 cs[Mm];
    int b = blockIdx.x;
    const float INFV = __int_as_float(0x7f800000);
    for (int m = threadIdx.x; m < Mm; m += 256) {
        size_t ci = ((size_t)b * Mm + m) * 3;
        float x = ic[ci], y = ic[ci + 1], z = ic[ci + 2];
        float s2 = imask[b * Mm + m] ? (x * x + y * y + z * z) : INFV;
        cs[m] = make_float4(x, y, z, s2);
    }
    __syncthreads();

    int n = blockIdx.y * 256 + threadIdx.x;
    size_t pidx = (size_t)b * Nn + n;
    float qx = pc[pidx * 3], qy = pc[pidx * 3 + 1], qz = pc[pidx * 3 + 2];
    float q2 = qx * qx + qy * qy + qz * qz;

    float d0 = INFV, d1 = INFV, d2v = INFV;
    int j0 = 0, j1 = 0, j2 = 0;
#pragma unroll 4
    for (int m = 0; m < Mm; m++) {
        float4 c = cs[m];
        float d = fmaxf(q2 + c.w - 2.0f * (qx * c.x + qy * c.y + qz * c.z), 0.0f);
        if (d < d2v) {
            if (d < d1) {
                d2v = d1; j2 = j1;
                if (d < d0) { d1 = d0; j1 = j0; d0 = d; j0 = m; }
                else        { d1 = d;  j1 = m; }
            } else { d2v = d; j2 = m; }
        }
    }
    float w0 = 1.0f / fmaxf(sqrtf(d0),  1e-6f);
    float w1 = 1.0f / fmaxf(sqrtf(d1),  1e-6f);
    float w2 = 1.0f / fmaxf(sqrtf(d2v), 1e-6f);
    float inv = 1.0f / fmaxf(w0 + w1 + w2, 1e-6f);
    size_t base = pidx * 3;
    knn_idx[base + 0] = b * Mm + j0;
    knn_idx[base + 1] = b * Mm + j1;
    knn_idx[base + 2] = b * Mm + j2;
    knn_w[base + 0] = w0 * inv;
    knn_w[base + 1] = w1 * inv;
    knn_w[base + 2] = w2 * inv;
}

// ---------------- K4: gather + concat + LN, fp16 permuted store -----------------
__global__ __launch_bounds__(128)
void fin_ln_kernel(const float* __restrict__ pt, const int* __restrict__ pvm,
                   __half* __restrict__ out) {
    int p = blockIdx.x, tid = threadIdx.x;
    float4 v;
    if (tid < 64) {
        v = *(const float4*)&pt[(size_t)p * ODim + tid * 4];
    } else {
        int base = p * 3;
        int i0 = g_knn_idx[base], i1 = g_knn_idx[base + 1], i2 = g_knn_idx[base + 2];
        float w0 = g_knn_w[base], w1 = g_knn_w[base + 1], w2 = g_knn_w[base + 2];
        int o = (tid - 64) * 4;
        float4 f0 = *(const float4*)&g_imgfeat[(size_t)i0 * ODim + o];
        float4 f1 = *(const float4*)&g_imgfeat[(size_t)i1 * ODim + o];
        float4 f2 = *(const float4*)&g_imgfeat[(size_t)i2 * ODim + o];
        float pv = pvm[p] ? 1.0f : 0.0f;
        v.x = (w0 * f0.x + w1 * f1.x + w2 * f2.x) * pv;
        v.y = (w0 * f0.y + w1 * f1.y + w2 * f2.y) * pv;
        v.z = (w0 * f0.z + w1 * f1.z + w2 * f2.z) * pv;
        v.w = (w0 * f0.w + w1 * f1.w + w2 * f2.w) * pv;
    }
    float s  = v.x + v.y + v.z + v.w;
    float ss = v.x * v.x + v.y * v.y + v.z * v.z + v.w * v.w;
    float2 r = block_reduce2(s, ss);
    float mean = r.x * (1.0f / 512.0f);
    float var  = fmaxf(r.y * (1.0f / 512.0f) - mean * mean, 0.0f);
    float rstd = rsqrtf(var + 1e-5f);
    __half* orow = out + (size_t)p * 512;
    int c = tid * 4;
    __half2 o01, o23;
    o01.x = __float2half_rn((v.x - mean) * rstd);
    o01.y = __float2half_rn((v.y - mean) * rstd);
    o23.x = __float2half_rn((v.z - mean) * rstd);
    o23.y = __float2half_rn((v.w - mean) * rstd);
    *(__half2*)(orow + permk(c))     = o01;
    *(__half2*)(orow + permk(c + 2)) = o23;
}

// ---------------- launch ---------------------------------------------------------
extern "C" void kernel_launch(void* const* d_in, const int* in_sizes, int n_in,
                              void* d_out, int out_size) {
    const float* pt      = (const float*)d_in[0];
    const float* pc      = (const float*)d_in[1];
    const float* it      = (const float*)d_in[2];
    const float* icd     = (const float*)d_in[3];
    const int*   pvm     = (const int*)d_in[4];
    const int*   ivm     = (const int*)d_in[5];
    const float* ip_ln_g = (const float*)d_in[6];
    const float* ip_ln_b = (const float*)d_in[7];
    const float* ip_w1   = (const float*)d_in[8];
    const float* ip_b1   = (const float*)d_in[9];
    const float* ip_w2   = (const float*)d_in[10];
    const float* ip_b2   = (const float*)d_in[11];
    const float* g_ln_g  = (const float*)d_in[12];
    const float* g_ln_b  = (const float*)d_in[13];
    const float* g_w1    = (const float*)d_in[14];
    const float* g_b1    = (const float*)d_in[15];
    const float* g_w2    = (const float*)d_in[16];
    const float* g_b2    = (const float*)d_in[17];
    const float* d_ln_g  = (const float*)d_in[18];
    const float* d_ln_b  = (const float*)d_in[19];
    const float* d_w1    = (const float*)d_in[20];
    const float* d_b1    = (const float*)d_in[21];
    const float* d_w2    = (const float*)d_in[22];
    const float* d_b2    = (const float*)d_in[23];
    float* out = (float*)d_out;

    __half *xln, *hbuf, *finln, *wt_ip1, *wt_gd1, *wt_ip2, *wt_g2, *wt_d2;
    float *imgf, *gate, *knnw, *bpip, *bpgd;
    int* knni;
    cudaGetSymbolAddress((void**)&xln,    g_xln);
    cudaGetSymbolAddress((void**)&hbuf,   g_hbuf);
    cudaGetSymbolAddress((void**)&imgf,   g_imgfeat);
    cudaGetSymbolAddress((void**)&finln,  g_finln);
    cudaGetSymbolAddress((void**)&gate,   g_gate);
    cudaGetSymbolAddress((void**)&knni,   g_knn_idx);
    cudaGetSymbolAddress((void**)&knnw,   g_knn_w);
    cudaGetSymbolAddress((void**)&wt_ip1, g_wt_ip1);
    cudaGetSymbolAddress((void**)&wt_gd1, g_wt_gd1);
    cudaGetSymbolAddress((void**)&wt_ip2, g_wt_ip2);
    cudaGetSymbolAddress((void**)&wt_g2,  g_wt_g2);
    cudaGetSymbolAddress((void**)&wt_d2,  g_wt_d2);
    cudaGetSymbolAddress((void**)&bpip,   g_bp_ip);
    cudaGetSymbolAddress((void**)&bpgd,   g_bp_gd);

    cudaFuncSetAttribute(mma_gemm<0>, cudaFuncAttributeMaxDynamicSharedMemorySize, SM_TOTAL);
    cudaFuncSetAttribute(mma_gemm<1>, cudaFuncAttributeMaxDynamicSharedMemorySize, SM_TOTAL);
    cudaFuncSetAttribute(mma_gemm<2>, cudaFuncAttributeMaxDynamicSharedMemorySize, SM_TOTAL);

    // ncu captures 0-based launch index 3 -> keep the img L1 GEMM there.
    fold_w1<<<(IDim * HDim + 255) / 256, 256>>>(ip_w1, ip_ln_g, wt_ip1, IDim, HDim);    // 0
    fold_b1<<<HDim / 64, 256>>>(ip_w1, ip_ln_b, ip_b1, bpip, IDim, HDim);               // 1
    ln_img_kernel<<<ROWS_IMG, 256>>>(it, xln);                                          // 2

    // 3: image MLP layer 1 (PROFILED launch)
    mma_gemm<1><<<dim3(HDim / 128, ROWS_IMG / 128), 256, SM_TOTAL>>>(
        xln, IDim, wt_ip1, bpip, hbuf, IDim, HDim, nullptr, nullptr, nullptr);

    transpose_k<<<(HDim * ODim + 255) / 256, 256>>>(ip_w2, wt_ip2, HDim, ODim);         // 4
    // 5: image MLP layer 2
    mma_gemm<0><<<dim3(ODim / 128, ROWS_IMG / 128), 256, SM_TOTAL>>>(
        hbuf, HDim, wt_ip2, ip_b2, imgf, HDim, ODim, nullptr, nullptr, nullptr);

    // remaining prep (independent of image path)
    fold_w1<<<(HDim * HDim + 255) / 256, 256>>>(g_w1, g_ln_g, wt_gd1, HDim, HDim);      // 6
    fold_w1<<<(HDim * HDim + 255) / 256, 256>>>(d_w1, d_ln_g, wt_gd1 + (size_t)HDim * HDim,
                                                HDim, HDim);                            // 7
    fold_b1<<<HDim / 64, 256>>>(g_w1, g_ln_b, g_b1, bpgd, HDim, HDim);                  // 8
    fold_b1<<<HDim / 64, 256>>>(d_w1, d_ln_b, d_b1, bpgd + HDim, HDim, HDim);           // 9
    transpose_k<<<(HDim * ODim + 255) / 256, 256>>>(g_w2, wt_g2, HDim, ODim);           // 10
    transpose_k<<<(HDim * ODim + 255) / 256, 256>>>(d_w2, wt_d2, HDim, ODim);           // 11

    knn_kernel<<<dim3(Bb, Nn / 256), 256>>>(pc, icd, ivm, knni, knnw);                  // 12
    fin_ln_kernel<<<ROWS_PT, 128>>>(pt, pvm, finln);                                    // 13

    // 14: fused gate|delta layer 1 -> hbuf [ROWS_PT, 1024]
    mma_gemm<1><<<dim3((2 * HDim) / 128, ROWS_PT / 128), 256, SM_TOTAL>>>(
        finln, 2 * ODim, wt_gd1, bpgd, hbuf, 2 * ODim, 2 * HDim, nullptr, nullptr, nullptr);

    // 15: gate layer 2 -> g_gate (fp32, pre-sigmoid)
    mma_gemm<0><<<dim3(ODim / 128, ROWS_PT / 128), 256, SM_TOTAL>>>(
        hbuf, 2 * HDim, wt_g2, g_b2, gate, HDim, ODim, nullptr, nullptr, nullptr);

    // 16: delta layer 2 + fused final combine
    mma_gemm<2><<<dim3(ODim / 128, ROWS_PT / 128), 256, SM_TOTAL>>>(
        hbuf + HDim, 2 * HDim, wt_d2, d_b2, out, HDim, ODim, gate, pt, pvm);
}

// round 12
// speedup vs baseline: 1.0273x; 1.0273x over previous
#include <cuda_runtime.h>
#include <cuda_fp16.h>
#include <math.h>
#include <stdint.h>

// Problem dims (fixed by the dataset)
#define Bb   16
#define Nn   4096
#define Mm   1024
#define IDim 768
#define HDim 512
#define ODim 256
#define ROWS_IMG (Bb*Mm)   // 16384
#define ROWS_PT  (Bb*Nn)   // 65536

// ---------------- scratch (device globals; no allocation allowed) -------------
__device__ __align__(16) __half g_xln[ROWS_IMG * IDim];          // LN img tokens (fp16, permuted)
__device__ __align__(16) __half g_hbuf[ROWS_PT * 2 * HDim];      // hidden (fp16, permuted)
__device__ __align__(16) __half g_imgfeat[ROWS_IMG * ODim];      // image MLP out (fp16 plain)
__device__ __align__(16) __half g_finln[ROWS_PT * (2 * ODim)];   // fin̂ (fp16, permuted)
__device__ int   g_knn_idx[ROWS_PT * 3];
__device__ float g_knn_w[ROWS_PT * 3];
// transposed (LN-folded) weights: [N,K] K-major, fp16, permuted
__device__ __align__(16) __half g_wt_ip1[HDim * IDim];
__device__ __align__(16) __half g_wt_gd1[(2 * HDim) * HDim];     // fused gate|delta layer-1
__device__ __align__(16) __half g_wt_ip2[ODim * HDim];
__device__ __align__(16) __half g_wt_g2[ODim * HDim];
__device__ __align__(16) __half g_wt_d2[ODim * HDim];
__device__ float g_bp_ip[HDim];
__device__ float g_bp_gd[2 * HDim];                              // fused gate|delta bias

// ---------------- helpers ------------------------------------------------------
// 32-wide k permutation: places a thread's mma fragments for BOTH 16-k steps of
// a 32-k tile into one contiguous 16B chunk (chunk index = (k>>1)&3):
//   pos = ((k>>1)&3)<<3 | ((k>>4)&1)<<2 | ((k>>3)&1)<<1 | (k&1)
__device__ __host__ __forceinline__ int permk(int k) {
    return (k & ~31) | (((k >> 1) & 3) << 3) | (((k >> 4) & 1) << 2)
         | (((k >> 3) & 1) << 1) | (k & 1);
}
__device__ __forceinline__ float gelu_f(float x) {
    return 0.5f * x * (1.0f + erff(x * 0.70710678118654752f));
}
__device__ __forceinline__ float sigmoid_f(float x) {
    return 1.0f / (1.0f + __expf(-x));
}
__device__ __forceinline__ float2 block_reduce2(float s, float ss) {
    __shared__ float sh[64];
    int lane = threadIdx.x & 31, w = threadIdx.x >> 5;
#pragma unroll
    for (int o = 16; o; o >>= 1) {
        s  += __shfl_down_sync(0xffffffffu, s,  o);
        ss += __shfl_down_sync(0xffffffffu, ss, o);
    }
    if (lane == 0) { sh[w] = s; sh[32 + w] = ss; }
    __syncthreads();
    int nw = (blockDim.x + 31) >> 5;
    if (w == 0) {
        s  = (lane < nw) ? sh[lane]      : 0.0f;
        ss = (lane < nw) ? sh[32 + lane] : 0.0f;
#pragma unroll
        for (int o = 16; o; o >>= 1) {
            s  += __shfl_down_sync(0xffffffffu, s,  o);
            ss += __shfl_down_sync(0xffffffffu, ss, o);
        }
        if (lane == 0) { sh[0] = s; sh[32] = ss; }
    }
    __syncthreads();
    return make_float2(sh[0], sh[32]);
}

// ---------------- K0a: elementwise LN-gain fold + transpose (fp16, permuted) ----
__global__ void fold_w1(const float* __restrict__ W, const float* __restrict__ gain,
                        __half* __restrict__ Wt, int Kd, int Nc) {
    int idx = blockIdx.x * blockDim.x + threadIdx.x;
    if (idx >= Kd * Nc) return;
    int k = idx / Nc, n = idx % Nc;
    Wt[(size_t)n * Kd + permk(k)] = __float2half_rn(gain[k] * W[idx]);
}
// ---------------- K0b: bias fold: b1p[n] = b1[n] + sum_k bln[k]*W[k,n] -----------
__global__ void fold_b1(const float* __restrict__ W, const float* __restrict__ bln,
                        const float* __restrict__ b1, float* __restrict__ b1p,
                        int Kd, int Nc) {
    __shared__ float sh[256];
    int nl = threadIdx.x & 63, ks = threadIdx.x >> 6;
    int n = blockIdx.x * 64 + nl;
    float acc = 0.0f;
    for (int k = ks; k < Kd; k += 4)
        acc += bln[k] * W[(size_t)k * Nc + n];
    sh[threadIdx.x] = acc;
    __syncthreads();
    if (ks == 0)
        b1p[n] = b1[n] + sh[nl] + sh[64 + nl] + sh[128 + nl] + sh[192 + nl];
}
// ---------------- K0c: plain transpose (fp16, permuted) -------------------------
__global__ void transpose_k(const float* __restrict__ W, __half* __restrict__ Wt,
                            int Kd, int Nc) {
    int idx = blockIdx.x * blockDim.x + threadIdx.x;
    if (idx >= Kd * Nc) return;
    int k = idx / Nc, n = idx % Nc;
    Wt[(size_t)n * Kd + permk(k)] = __float2half_rn(W[idx]);
}

// ---------------- K1: LN (normalize only), fp16 permuted store ------------------
__global__ void ln_img_kernel(const float* __restrict__ x, __half* __restrict__ y) {
    int row = blockIdx.x, tid = threadIdx.x;
    const float* xr = x + (size_t)row * IDim;
    float v0 = xr[tid], v1 = xr[tid + 256], v2 = xr[tid + 512];
    float s = v0 + v1 + v2;
    float ss = v0 * v0 + v1 * v1 + v2 * v2;
    float2 r = block_reduce2(s, ss);
    float mean = r.x * (1.0f / 768.0f);
    float var  = fmaxf(r.y * (1.0f / 768.0f) - mean * mean, 0.0f);
    float rstd = rsqrtf(var + 1e-5f);
    __half* yr = y + (size_t)row * IDim;
    yr[permk(tid)]       = __float2half_rn((v0 - mean) * rstd);
    yr[permk(tid + 256)] = __float2half_rn((v1 - mean) * rstd);
    yr[permk(tid + 512)] = __float2half_rn((v2 - mean) * rstd);
}

// ---------------- GEMM core: fp16 m16n8k16 mma.sync -----------------------------
#define KTILE   32
#define ROWB    64                           // bytes/row, XOR swizzle (no pad)
#define TILE_B  (128 * ROWB)                 // 8192 bytes
#define STAGE_B (2 * TILE_B)                 // 16384
#define STAGES  4
#define STAGES_BYTES (STAGES * STAGE_B)      // 65536
#define GSTASH_BYTES (256 * 32 * 4)          // 32768: 32 __half2 per thread
#define SM_GEMM  STAGES_BYTES                // plain GEMM smem
#define SM_FUSED (STAGES_BYTES + GSTASH_BYTES)

#define CPA_COMMIT() asm volatile("cp.async.commit_group;" ::: "memory")
#define CPA_WAIT2()  asm volatile("cp.async.wait_group 2;" ::: "memory")
#define CPA_WAIT0()  asm volatile("cp.async.wait_group 0;" ::: "memory")

__device__ __forceinline__ uint32_t smem_u32(const void* p) {
    uint32_t a;
    asm("{ .reg .u64 t; cvta.to.shared.u64 t, %1; cvt.u32.u64 %0, t; }" : "=r"(a) : "l"(p));
    return a;
}

// one 128x32(fp16) tile: 512 x 16B chunks, 2 per thread; chunk col c' = c ^ (r&3)
__device__ __forceinline__ void load_tile(uint32_t sbase, const __half* gbase, int ld) {
    int t = threadIdx.x;
#pragma unroll
    for (int i = 0; i < 2; i++) {
        int idx = t + i * 256;
        int r = idx >> 2, c = idx & 3;
        uint32_t so = sbase + (uint32_t)(r * ROWB + 16 * (c ^ (r & 3)));
        const __half* gp = gbase + (size_t)r * ld + c * 8;
        asm volatile("cp.async.cg.shared.global [%0], [%1], 16;" :: "r"(so), "l"(gp));
    }
}

__device__ __forceinline__ void mma_f16(float* d, uint32_t a0, uint32_t a1, uint32_t a2,
                                        uint32_t a3, uint32_t b0, uint32_t b1) {
    asm volatile(
        "mma.sync.aligned.m16n8k16.row.col.f32.f16.f16.f32 "
        "{%0,%1,%2,%3}, {%4,%5,%6,%7}, {%8,%9}, {%0,%1,%2,%3};"
        : "+f"(d[0]), "+f"(d[1]), "+f"(d[2]), "+f"(d[3])
        : "r"(a0), "r"(a1), "r"(a2), "r"(a3), "r"(b0), "r"(b1));
}

// shared 128x128-tile mainloop; acc zeroed inside. a_base/b_base: per-thread
// swizzled byte offsets (same for every stage).
__device__ __forceinline__ void gemm_mainloop(char* smem, uint32_t sb,
        const __half* Ag, int lda, const __half* Bg, int ldb, int NK,
        int a_base, int b_base, float acc[4][4][4]) {
#pragma unroll
    for (int mf = 0; mf < 4; mf++)
#pragma unroll
        for (int nf = 0; nf < 4; nf++)
#pragma unroll
            for (int e = 0; e < 4; e++) acc[mf][nf][e] = 0.0f;

#pragma unroll
    for (int p = 0; p < 3; p++) {
        load_tile(sb + p * STAGE_B,          Ag + p * KTILE, lda);
        load_tile(sb + p * STAGE_B + TILE_B, Bg + p * KTILE, ldb);
        CPA_COMMIT();
    }
    for (int kt = 0; kt < NK; kt++) {
        CPA_WAIT2();
        __syncthreads();
        if (kt + 3 < NK) {
            int st = (kt + 3) % STAGES;
            load_tile(sb + st * STAGE_B,          Ag + (size_t)(kt + 3) * KTILE, lda);
            load_tile(sb + st * STAGE_B + TILE_B, Bg + (size_t)(kt + 3) * KTILE, ldb);
        }
        CPA_COMMIT();

        int s = kt % STAGES;
        const char* As = smem + s * STAGE_B + a_base;
        const char* Bs = smem + s * STAGE_B + TILE_B + b_base;
        uint4 af[8], bq[4];
#pragma unroll
        for (int mf = 0; mf < 4; mf++) {
            af[2 * mf]     = *(const uint4*)(As + mf * (16 * ROWB));
            af[2 * mf + 1] = *(const uint4*)(As + mf * (16 * ROWB) + 8 * ROWB);
        }
#pragma unroll
        for (int nf = 0; nf < 4; nf++)
            bq[nf] = *(const uint4*)(Bs + nf * (8 * ROWB));
#pragma unroll
        for (int mf = 0; mf < 4; mf++)
#pragma unroll
            for (int nf = 0; nf < 4; nf++) {
                mma_f16(acc[mf][nf],
                        af[2 * mf].x, af[2 * mf + 1].x, af[2 * mf].y, af[2 * mf + 1].y,
                        bq[nf].x, bq[nf].y);
                mma_f16(acc[mf][nf],
                        af[2 * mf].z, af[2 * mf + 1].z, af[2 * mf].w, af[2 * mf + 1].w,
                        bq[nf].z, bq[nf].w);
            }
    }
}

// ---------------- K2: standalone GEMM --------------------------------------------
// ACT: 0 -> fp16 plain store (imgfeat), 1 -> gelu + fp16 permuted store (hbuf)
template <int ACT>
__global__ __launch_bounds__(256, 2)
void mma_gemm(const __half* __restrict__ A, int lda, const __half* __restrict__ Bt,
              const float* __restrict__ bias, __half* __restrict__ C,
              int Kd, int Nc) {
    extern __shared__ char smem[];
    uint32_t sb = smem_u32(smem);
    int tid = threadIdx.x, wid = tid >> 5, lane = tid & 31;
    int wm = wid & 1, wn = wid >> 1;
    int g = lane >> 2, i4 = lane & 3;
    int row0 = blockIdx.y * 128, col0 = blockIdx.x * 128;

    const int sc = 16 * (i4 ^ (g & 3));
    const int a_base = (wm * 64 + g) * ROWB + sc;
    const int b_base = (wn * 32 + g) * ROWB + sc;

    float acc[4][4][4];
    gemm_mainloop(smem, sb, A + (size_t)row0 * lda, lda,
                  Bt + (size_t)col0 * Kd, Kd, Kd / KTILE, a_base, b_base, acc);

#pragma unroll
    for (int mf = 0; mf < 4; mf++) {
        int r_lo = row0 + wm * 64 + mf * 16 + g;
#pragma unroll
        for (int nf = 0; nf < 4; nf++) {
            int col = col0 + wn * 32 + nf * 8 + i4 * 2;
            float b0 = bias[col], b1 = bias[col + 1];
#pragma unroll
            for (int h = 0; h < 2; h++) {
                int row = r_lo + h * 8;
                float v0 = acc[mf][nf][h * 2 + 0] + b0;
                float v1 = acc[mf][nf][h * 2 + 1] + b1;
                __half2 o;
                if (ACT == 1) {
                    o.x = __float2half_rn(gelu_f(v0));
                    o.y = __float2half_rn(gelu_f(v1));
                    *(__half2*)(C + (size_t)row * Nc + permk(col)) = o;
                } else {
                    o.x = __float2half_rn(v0);
                    o.y = __float2half_rn(v1);
                    *(__half2*)(C + (size_t)row * Nc + col) = o;
                }
            }
        }
    }
}

// ---------------- K2b: fused gate-L2 + delta-L2 + final combine ------------------
// loop1: gate = sigmoid(hbuf[:, :512] @ wt_g2 + g_b2)  -> smem stash (per-thread)
// loop2: delta =        hbuf[:, 512:] @ wt_d2 + d_b2
// out = (pt + gate * delta) * pv
__global__ __launch_bounds__(256, 2)
void fused_gd2(const __half* __restrict__ hb, const __half* __restrict__ Bg2,
               const __half* __restrict__ Bd2,
               const float* __restrict__ gbias, const float* __restrict__ dbias,
               const float* __restrict__ ptb, const int* __restrict__ pvm,
               float* __restrict__ out) {
    extern __shared__ char smem[];
    uint32_t sb = smem_u32(smem);
    __half2* stash = (__half2*)(smem + STAGES_BYTES);
    int tid = threadIdx.x, wid = tid >> 5, lane = tid & 31;
    int wm = wid & 1, wn = wid >> 1;
    int g = lane >> 2, i4 = lane & 3;
    int row0 = blockIdx.y * 128, col0 = blockIdx.x * 128;

    const int sc = 16 * (i4 ^ (g & 3));
    const int a_base = (wm * 64 + g) * ROWB + sc;
    const int b_base = (wn * 32 + g) * ROWB + sc;
    const int NK = HDim / KTILE;   // 16

    float acc[4][4][4];
    // loop 1: gate
    gemm_mainloop(smem, sb, hb + (size_t)row0 * (2 * HDim), 2 * HDim,
                  Bg2 + (size_t)col0 * HDim, HDim, NK, a_base, b_base, acc);
    // stash sigmoid(gate): 32 __half2 slots PER THREAD (private; re-read by same thread)
    __half2* tst = stash + tid * 32;
#pragma unroll
    for (int mf = 0; mf < 4; mf++)
#pragma unroll
        for (int nf = 0; nf < 4; nf++) {
            int col = col0 + wn * 32 + nf * 8 + i4 * 2;
            float b0 = gbias[col], b1 = gbias[col + 1];
#pragma unroll
            for (int h = 0; h < 2; h++) {
                __half2 o;
                o.x = __float2half_rn(sigmoid_f(acc[mf][nf][h * 2 + 0] + b0));
                o.y = __float2half_rn(sigmoid_f(acc[mf][nf][h * 2 + 1] + b1));
                tst[(mf * 4 + nf) * 2 + h] = o;
            }
        }
    CPA_WAIT0();
    __syncthreads();   // stage buffers fully consumed before loop-2 prologue

    // loop 2: delta
    gemm_mainloop(smem, sb, hb + (size_t)row0 * (2 * HDim) + HDim, 2 * HDim,
                  Bd2 + (size_t)col0 * HDim, HDim, NK, a_base, b_base, acc);

    // epilogue: combine
#pragma unroll
    for (int mf = 0; mf < 4; mf++) {
        int r_lo = row0 + wm * 64 + mf * 16 + g;
#pragma unroll
        for (int nf = 0; nf < 4; nf++) {
            int col = col0 + wn * 32 + nf * 8 + i4 * 2;
            float b0 = dbias[col], b1 = dbias[col + 1];
#pragma unroll
            for (int h = 0; h < 2; h++) {
                int row = r_lo + h * 8;
                float v0 = acc[mf][nf][h * 2 + 0] + b0;
                float v1 = acc[mf][nf][h * 2 + 1] + b1;
                __half2 gt = tst[(mf * 4 + nf) * 2 + h];
                size_t off = (size_t)row * ODim + col;
                float2 p4 = *(const float2*)(ptb + off);
                float m = pvm[row] ? 1.0f : 0.0f;
                float o0 = (p4.x + __half2float(gt.x) * v0) * m;
                float o1 = (p4.y + __half2float(gt.y) * v1) * m;
                *(float2*)(out + off) = make_float2(o0, o1);
            }
        }
    }
}

// ---------------- K3: kNN top-3 + inverse-distance weights ----------------------
__global__ __launch_bounds__(256)
void knn_kernel(const float* __restrict__ pc, const float* __restrict__ ic,
                const int* __restrict__ imask,
                int* __restrict__ knn_idx, float* __restrict__ knn_w) {
    __shared__ float4 cs[Mm];
    int b = blockIdx.x;
    const float INFV = __int_as_float(0x7f800000);
    for (int m = threadIdx.x; m < Mm; m += 256) {
        size_t ci = ((size_t)b * Mm + m) * 3;
        float x = ic[ci], y = ic[ci + 1], z = ic[ci + 2];
        float s2 = imask[b * Mm + m] ? (x * x + y * y + z * z) : INFV;
        cs[m] = make_float4(x, y, z, s2);
    }
    __syncthreads();

    int n = blockIdx.y * 256 + threadIdx.x;
    size_t pidx = (size_t)b * Nn + n;
    float qx = pc[pidx * 3], qy = pc[pidx * 3 + 1], qz = pc[pidx * 3 + 2];
    float q2 = qx * qx + qy * qy + qz * qz;

    float d0 = INFV, d1 = INFV, d2v = INFV;
    int j0 = 0, j1 = 0, j2 = 0;
#pragma unroll 4
    for (int m = 0; m < Mm; m++) {
        float4 c = cs[m];
        float d = fmaxf(q2 + c.w - 2.0f * (qx * c.x + qy * c.y + qz * c.z), 0.0f);
        if (d < d2v) {
            if (d < d1) {
                d2v = d1; j2 = j1;
                if (d < d0) { d1 = d0; j1 = j0; d0 = d; j0 = m; }
                else        { d1 = d;  j1 = m; }
            } else { d2v = d; j2 = m; }
        }
    }
    float w0 = 1.0f / fmaxf(sqrtf(d0),  1e-6f);
    float w1 = 1.0f / fmaxf(sqrtf(d1),  1e-6f);
    float w2 = 1.0f / fmaxf(sqrtf(d2v), 1e-6f);
    float inv = 1.0f / fmaxf(w0 + w1 + w2, 1e-6f);
    size_t base = pidx * 3;
    knn_idx[base + 0] = b * Mm + j0;
    knn_idx[base + 1] = b * Mm + j1;
    knn_idx[base + 2] = b * Mm + j2;
    knn_w[base + 0] = w0 * inv;
    knn_w[base + 1] = w1 * inv;
    knn_w[base + 2] = w2 * inv;
}

// ---------------- K4: gather (fp16 imgfeat) + concat + LN, fp16 permuted --------
__global__ __launch_bounds__(128)
void fin_ln_kernel(const float* __restrict__ pt, const int* __restrict__ pvm,
                   __half* __restrict__ out) {
    int p = blockIdx.x, tid = threadIdx.x;
    float4 v;
    if (tid < 64) {
        v = *(const float4*)&pt[(size_t)p * ODim + tid * 4];
    } else {
        int base = p * 3;
        int i0 = g_knn_idx[base], i1 = g_knn_idx[base + 1], i2 = g_knn_idx[base + 2];
        float w0 = g_knn_w[base], w1 = g_knn_w[base + 1], w2 = g_knn_w[base + 2];
        int o = (tid - 64) * 4;
        __half2 a0 = *(const __half2*)&g_imgfeat[(size_t)i0 * ODim + o];
        __half2 a1 = *(const __half2*)&g_imgfeat[(size_t)i0 * ODim + o + 2];
        __half2 b0 = *(const __half2*)&g_imgfeat[(size_t)i1 * ODim + o];
        __half2 b1 = *(const __half2*)&g_imgfeat[(size_t)i1 * ODim + o + 2];
        __half2 c0 = *(const __half2*)&g_imgfeat[(size_t)i2 * ODim + o];
        __half2 c1 = *(const __half2*)&g_imgfeat[(size_t)i2 * ODim + o + 2];
        float pv = pvm[p] ? 1.0f : 0.0f;
        v.x = (w0 * __half2float(a0.x) + w1 * __half2float(b0.x) + w2 * __half2float(c0.x)) * pv;
        v.y = (w0 * __half2float(a0.y) + w1 * __half2float(b0.y) + w2 * __half2float(c0.y)) * pv;
        v.z = (w0 * __half2float(a1.x) + w1 * __half2float(b1.x) + w2 * __half2float(c1.x)) * pv;
        v.w = (w0 * __half2float(a1.y) + w1 * __half2float(b1.y) + w2 * __half2float(c1.y)) * pv;
    }
    float s  = v.x + v.y + v.z + v.w;
    float ss = v.x * v.x + v.y * v.y + v.z * v.z + v.w * v.w;
    float2 r = block_reduce2(s, ss);
    float mean = r.x * (1.0f / 512.0f);
    float var  = fmaxf(r.y * (1.0f / 512.0f) - mean * mean, 0.0f);
    float rstd = rsqrtf(var + 1e-5f);
    __half* orow = out + (size_t)p * 512;
    int c = tid * 4;
    __half2 o01, o23;
    o01.x = __float2half_rn((v.x - mean) * rstd);
    o01.y = __float2half_rn((v.y - mean) * rstd);
    o23.x = __float2half_rn((v.z - mean) * rstd);
    o23.y = __float2half_rn((v.w - mean) * rstd);
    *(__half2*)(orow + permk(c))     = o01;
    *(__half2*)(orow + permk(c + 2)) = o23;
}

// ---------------- launch ---------------------------------------------------------
extern "C" void kernel_launch(void* const* d_in, const int* in_sizes, int n_in,
                              void* d_out, int out_size) {
    const float* pt      = (const float*)d_in[0];
    const float* pc      = (const float*)d_in[1];
    const float* it      = (const float*)d_in[2];
    const float* icd     = (const float*)d_in[3];
    const int*   pvm     = (const int*)d_in[4];
    const int*   ivm     = (const int*)d_in[5];
    const float* ip_ln_g = (const float*)d_in[6];
    const float* ip_ln_b = (const float*)d_in[7];
    const float* ip_w1   = (const float*)d_in[8];
    const float* ip_b1   = (const float*)d_in[9];
    const float* ip_w2   = (const float*)d_in[10];
    const float* ip_b2   = (const float*)d_in[11];
    const float* g_ln_g  = (const float*)d_in[12];
    const float* g_ln_b  = (const float*)d_in[13];
    const float* g_w1    = (const float*)d_in[14];
    const float* g_b1    = (const float*)d_in[15];
    const float* g_w2    = (const float*)d_in[16];
    const float* g_b2    = (const float*)d_in[17];
    const float* d_ln_g  = (const float*)d_in[18];
    const float* d_ln_b  = (const float*)d_in[19];
    const float* d_w1    = (const float*)d_in[20];
    const float* d_b1    = (const float*)d_in[21];
    const float* d_w2    = (const float*)d_in[22];
    const float* d_b2    = (const float*)d_in[23];
    float* out = (float*)d_out;

    __half *xln, *hbuf, *imgf, *finln, *wt_ip1, *wt_gd1, *wt_ip2, *wt_g2, *wt_d2;
    float *knnw, *bpip, *bpgd;
    int* knni;
    cudaGetSymbolAddress((void**)&xln,    g_xln);
    cudaGetSymbolAddress((void**)&hbuf,   g_hbuf);
    cudaGetSymbolAddress((void**)&imgf,   g_imgfeat);
    cudaGetSymbolAddress((void**)&finln,  g_finln);
    cudaGetSymbolAddress((void**)&knni,   g_knn_idx);
    cudaGetSymbolAddress((void**)&knnw,   g_knn_w);
    cudaGetSymbolAddress((void**)&wt_ip1, g_wt_ip1);
    cudaGetSymbolAddress((void**)&wt_gd1, g_wt_gd1);
    cudaGetSymbolAddress((void**)&wt_ip2, g_wt_ip2);
    cudaGetSymbolAddress((void**)&wt_g2,  g_wt_g2);
    cudaGetSymbolAddress((void**)&wt_d2,  g_wt_d2);
    cudaGetSymbolAddress((void**)&bpip,   g_bp_ip);
    cudaGetSymbolAddress((void**)&bpgd,   g_bp_gd);

    cudaFuncSetAttribute(mma_gemm<0>, cudaFuncAttributeMaxDynamicSharedMemorySize, SM_GEMM);
    cudaFuncSetAttribute(mma_gemm<1>, cudaFuncAttributeMaxDynamicSharedMemorySize, SM_GEMM);
    cudaFuncSetAttribute(fused_gd2,  cudaFuncAttributeMaxDynamicSharedMemorySize, SM_FUSED);

    // ncu captures 0-based launch index 3 -> keep the img L1 GEMM there.
    fold_w1<<<(IDim * HDim + 255) / 256, 256>>>(ip_w1, ip_ln_g, wt_ip1, IDim, HDim);    // 0
    fold_b1<<<HDim / 64, 256>>>(ip_w1, ip_ln_b, ip_b1, bpip, IDim, HDim);               // 1
    ln_img_kernel<<<ROWS_IMG, 256>>>(it, xln);                                          // 2

    // 3: image MLP layer 1 (PROFILED launch)
    mma_gemm<1><<<dim3(HDim / 128, ROWS_IMG / 128), 256, SM_GEMM>>>(
        xln, IDim, wt_ip1, bpip, hbuf, IDim, HDim);

    transpose_k<<<(HDim * ODim + 255) / 256, 256>>>(ip_w2, wt_ip2, HDim, ODim);         // 4
    // 5: image MLP layer 2 -> imgfeat (fp16 plain)
    mma_gemm<0><<<dim3(ODim / 128, ROWS_IMG / 128), 256, SM_GEMM>>>(
        hbuf, HDim, wt_ip2, ip_b2, imgf, HDim, ODim);

    // remaining prep
    fold_w1<<<(HDim * HDim + 255) / 256, 256>>>(g_w1, g_ln_g, wt_gd1, HDim, HDim);      // 6
    fold_w1<<<(HDim * HDim + 255) / 256, 256>>>(d_w1, d_ln_g, wt_gd1 + (size_t)HDim * HDim,
                                                HDim, HDim);                            // 7
    fold_b1<<<HDim / 64, 256>>>(g_w1, g_ln_b, g_b1, bpgd, HDim, HDim);                  // 8
    fold_b1<<<HDim / 64, 256>>>(d_w1, d_ln_b, d_b1, bpgd + HDim, HDim, HDim);           // 9
    transpose_k<<<(HDim * ODim + 255) / 256, 256>>>(g_w2, wt_g2, HDim, ODim);           // 10
    transpose_k<<<(HDim * ODim + 255) / 256, 256>>>(d_w2, wt_d2, HDim, ODim);           // 11

    knn_kernel<<<dim3(Bb, Nn / 256), 256>>>(pc, icd, ivm, knni, knnw);                  // 12
    fin_ln_kernel<<<ROWS_PT, 128>>>(pt, pvm, finln);                                    // 13

    // 14: fused gate|delta layer 1 -> hbuf [ROWS_PT, 1024]
    mma_gemm<1><<<dim3((2 * HDim) / 128, ROWS_PT / 128), 256, SM_GEMM>>>(
        finln, 2 * ODim, wt_gd1, bpgd, hbuf, 2 * ODim, 2 * HDim);

    // 15: fused gate-L2 + delta-L2 + combine -> out
    fused_gd2<<<dim3(ODim / 128, ROWS_PT / 128), 256, SM_FUSED>>>(
        hbuf, wt_g2, wt_d2, g_b2, d_b2, pt, pvm, out);
}

// round 13
// speedup vs baseline: 1.0324x; 1.0049x over previous
#include <cuda_runtime.h>
#include <cuda_fp16.h>
#include <math.h>
#include <stdint.h>

// Problem dims (fixed by the dataset)
#define Bb   16
#define Nn   4096
#define Mm   1024
#define IDim 768
#define HDim 512
#define ODim 256
#define ROWS_IMG (Bb*Mm)   // 16384
#define ROWS_PT  (Bb*Nn)   // 65536

// ---------------- scratch (device globals; no allocation allowed) -------------
__device__ __align__(16) __half g_xln[ROWS_IMG * IDim];          // LN img tokens (fp16, permuted)
__device__ __align__(16) __half g_hbuf[ROWS_PT * 2 * HDim];      // hidden (fp16, permuted)
__device__ __align__(16) __half g_imgfeat[ROWS_IMG * ODim];      // image MLP out (fp16 plain)
__device__ __align__(16) __half g_finln[ROWS_PT * (2 * ODim)];   // fin̂ (fp16, permuted)
__device__ int   g_knn_idx[ROWS_PT * 3];
__device__ float g_knn_w[ROWS_PT * 3];
// transposed (LN-folded) weights: [N,K] K-major, fp16, permuted
__device__ __align__(16) __half g_wt_ip1[HDim * IDim];
__device__ __align__(16) __half g_wt_gd1[(2 * HDim) * HDim];     // fused gate|delta layer-1
__device__ __align__(16) __half g_wt_ip2[ODim * HDim];
__device__ __align__(16) __half g_wt_g2[ODim * HDim];
__device__ __align__(16) __half g_wt_d2[ODim * HDim];
__device__ float g_bp_ip[HDim];
__device__ float g_bp_gd[2 * HDim];                              // fused gate|delta bias

// ---------------- helpers ------------------------------------------------------
// 32-wide k permutation: places a thread's mma fragments for BOTH 16-k steps of
// a 32-k tile into one contiguous 16B chunk (chunk index = (k>>1)&3):
//   pos = ((k>>1)&3)<<3 | ((k>>4)&1)<<2 | ((k>>3)&1)<<1 | (k&1)
__device__ __host__ __forceinline__ int permk(int k) {
    return (k & ~31) | (((k >> 1) & 3) << 3) | (((k >> 4) & 1) << 2)
         | (((k >> 3) & 1) << 1) | (k & 1);
}
__device__ __forceinline__ float gelu_f(float x) {
    return 0.5f * x * (1.0f + erff(x * 0.70710678118654752f));
}
__device__ __forceinline__ float sigmoid_f(float x) {
    return 1.0f / (1.0f + __expf(-x));
}
__device__ __forceinline__ float2 block_reduce2(float s, float ss) {
    __shared__ float sh[64];
    int lane = threadIdx.x & 31, w = threadIdx.x >> 5;
#pragma unroll
    for (int o = 16; o; o >>= 1) {
        s  += __shfl_down_sync(0xffffffffu, s,  o);
        ss += __shfl_down_sync(0xffffffffu, ss, o);
    }
    if (lane == 0) { sh[w] = s; sh[32 + w] = ss; }
    __syncthreads();
    int nw = (blockDim.x + 31) >> 5;
    if (w == 0) {
        s  = (lane < nw) ? sh[lane]      : 0.0f;
        ss = (lane < nw) ? sh[32 + lane] : 0.0f;
#pragma unroll
        for (int o = 16; o; o >>= 1) {
            s  += __shfl_down_sync(0xffffffffu, s,  o);
            ss += __shfl_down_sync(0xffffffffu, ss, o);
        }
        if (lane == 0) { sh[0] = s; sh[32] = ss; }
    }
    __syncthreads();
    return make_float2(sh[0], sh[32]);
}

// ---------------- K0a: elementwise LN-gain fold + transpose (fp16, permuted) ----
__global__ void fold_w1(const float* __restrict__ W, const float* __restrict__ gain,
                        __half* __restrict__ Wt, int Kd, int Nc) {
    int idx = blockIdx.x * blockDim.x + threadIdx.x;
    if (idx >= Kd * Nc) return;
    int k = idx / Nc, n = idx % Nc;
    Wt[(size_t)n * Kd + permk(k)] = __float2half_rn(gain[k] * W[idx]);
}
// ---------------- K0b: bias fold: b1p[n] = b1[n] + sum_k bln[k]*W[k,n] -----------
__global__ void fold_b1(const float* __restrict__ W, const float* __restrict__ bln,
                        const float* __restrict__ b1, float* __restrict__ b1p,
                        int Kd, int Nc) {
    __shared__ float sh[256];
    int nl = threadIdx.x & 63, ks = threadIdx.x >> 6;
    int n = blockIdx.x * 64 + nl;
    float acc = 0.0f;
    for (int k = ks; k < Kd; k += 4)
        acc += bln[k] * W[(size_t)k * Nc + n];
    sh[threadIdx.x] = acc;
    __syncthreads();
    if (ks == 0)
        b1p[n] = b1[n] + sh[nl] + sh[64 + nl] + sh[128 + nl] + sh[192 + nl];
}
// ---------------- K0c: plain transpose (fp16, permuted) -------------------------
__global__ void transpose_k(const float* __restrict__ W, __half* __restrict__ Wt,
                            int Kd, int Nc) {
    int idx = blockIdx.x * blockDim.x + threadIdx.x;
    if (idx >= Kd * Nc) return;
    int k = idx / Nc, n = idx % Nc;
    Wt[(size_t)n * Kd + permk(k)] = __float2half_rn(W[idx]);
}

// ---------------- K1: LN (normalize only), fp16 permuted store ------------------
__global__ void ln_img_kernel(const float* __restrict__ x, __half* __restrict__ y) {
    int row = blockIdx.x, tid = threadIdx.x;
    const float* xr = x + (size_t)row * IDim;
    float v0 = xr[tid], v1 = xr[tid + 256], v2 = xr[tid + 512];
    float s = v0 + v1 + v2;
    float ss = v0 * v0 + v1 * v1 + v2 * v2;
    float2 r = block_reduce2(s, ss);
    float mean = r.x * (1.0f / 768.0f);
    float var  = fmaxf(r.y * (1.0f / 768.0f) - mean * mean, 0.0f);
    float rstd = rsqrtf(var + 1e-5f);
    __half* yr = y + (size_t)row * IDim;
    yr[permk(tid)]       = __float2half_rn((v0 - mean) * rstd);
    yr[permk(tid + 256)] = __float2half_rn((v1 - mean) * rstd);
    yr[permk(tid + 512)] = __float2half_rn((v2 - mean) * rstd);
}

// ---------------- GEMM core: fp16 m16n8k16 mma.sync -----------------------------
#define KTILE   32
#define ROWB    64                           // bytes/row, XOR swizzle (no pad)
#define TILE_B  (128 * ROWB)                 // 8192 bytes
#define STAGE_B (2 * TILE_B)                 // 16384
#define STAGES  4                            // fused kernel: single-kt loop
#define STAGES_BYTES (STAGES * STAGE_B)      // 65536
#define PSTAGES 6                            // standalone: 3 pair-slots
#define PSTAGES_BYTES (PSTAGES * STAGE_B)    // 98304 -> still 2 CTAs/SM
#define GSTASH_BYTES (256 * 32 * 4)          // 32768: 32 __half2 per thread
#define SM_GEMM  PSTAGES_BYTES
#define SM_FUSED (STAGES_BYTES + GSTASH_BYTES)

#define CPA_COMMIT() asm volatile("cp.async.commit_group;" ::: "memory")
#define CPA_WAIT2()  asm volatile("cp.async.wait_group 2;" ::: "memory")
#define CPA_WAIT1()  asm volatile("cp.async.wait_group 1;" ::: "memory")
#define CPA_WAIT0()  asm volatile("cp.async.wait_group 0;" ::: "memory")

__device__ __forceinline__ uint32_t smem_u32(const void* p) {
    uint32_t a;
    asm("{ .reg .u64 t; cvta.to.shared.u64 t, %1; cvt.u32.u64 %0, t; }" : "=r"(a) : "l"(p));
    return a;
}

// one 128x32(fp16) tile: 512 x 16B chunks, 2 per thread; chunk col c' = c ^ (r&3)
__device__ __forceinline__ void load_tile(uint32_t sbase, const __half* gbase, int ld) {
    int t = threadIdx.x;
#pragma unroll
    for (int i = 0; i < 2; i++) {
        int idx = t + i * 256;
        int r = idx >> 2, c = idx & 3;
        uint32_t so = sbase + (uint32_t)(r * ROWB + 16 * (c ^ (r & 3)));
        const __half* gp = gbase + (size_t)r * ld + c * 8;
        asm volatile("cp.async.cg.shared.global [%0], [%1], 16;" :: "r"(so), "l"(gp));
    }
}

__device__ __forceinline__ void mma_f16(float* d, uint32_t a0, uint32_t a1, uint32_t a2,
                                        uint32_t a3, uint32_t b0, uint32_t b1) {
    asm volatile(
        "mma.sync.aligned.m16n8k16.row.col.f32.f16.f16.f32 "
        "{%0,%1,%2,%3}, {%4,%5,%6,%7}, {%8,%9}, {%0,%1,%2,%3};"
        : "+f"(d[0]), "+f"(d[1]), "+f"(d[2]), "+f"(d[3])
        : "r"(a0), "r"(a1), "r"(a2), "r"(a3), "r"(b0), "r"(b1));
}

// consume one 32-k stage: 12 x LDS.128 + 32 MMAs
__device__ __forceinline__ void consume_stage(const char* smem_stage,
        int a_base, int b_base, float acc[4][4][4]) {
    const char* As = smem_stage + a_base;
    const char* Bs = smem_stage + TILE_B + b_base;
    uint4 af[8], bq[4];
#pragma unroll
    for (int mf = 0; mf < 4; mf++) {
        af[2 * mf]     = *(const uint4*)(As + mf * (16 * ROWB));
        af[2 * mf + 1] = *(const uint4*)(As + mf * (16 * ROWB) + 8 * ROWB);
    }
#pragma unroll
    for (int nf = 0; nf < 4; nf++)
        bq[nf] = *(const uint4*)(Bs + nf * (8 * ROWB));
#pragma unroll
    for (int mf = 0; mf < 4; mf++)
#pragma unroll
        for (int nf = 0; nf < 4; nf++) {
            mma_f16(acc[mf][nf],
                    af[2 * mf].x, af[2 * mf + 1].x, af[2 * mf].y, af[2 * mf + 1].y,
                    bq[nf].x, bq[nf].y);
            mma_f16(acc[mf][nf],
                    af[2 * mf].z, af[2 * mf + 1].z, af[2 * mf].w, af[2 * mf + 1].w,
                    bq[nf].z, bq[nf].w);
        }
}

// paired mainloop (standalone GEMMs): 2 k-tiles per wait+barrier, 3 pair-slots.
// Requires NK even and NK >= 4.
__device__ __forceinline__ void gemm_mainloop2(char* smem, uint32_t sb,
        const __half* Ag, int lda, const __half* Bg, int ldb, int NK,
        int a_base, int b_base, float acc[4][4][4]) {
#pragma unroll
    for (int mf = 0; mf < 4; mf++)
#pragma unroll
        for (int nf = 0; nf < 4; nf++)
#pragma unroll
            for (int e = 0; e < 4; e++) acc[mf][nf][e] = 0.0f;

    const int NK2 = NK >> 1;
    // prologue: pairs 0,1 -> slots 0,1 (one commit group per pair)
#pragma unroll
    for (int p = 0; p < 2; p++) {
#pragma unroll
        for (int q = 0; q < 2; q++) {
            int st = 2 * p + q;
            load_tile(sb + st * STAGE_B,          Ag + (size_t)(2 * p + q) * KTILE, lda);
            load_tile(sb + st * STAGE_B + TILE_B, Bg + (size_t)(2 * p + q) * KTILE, ldb);
        }
        CPA_COMMIT();
    }
    for (int kp = 0; kp < NK2; kp++) {
        CPA_WAIT1();                 // pair kp resident (group i == pair i)
        __syncthreads();             // pair kp-1 fully consumed by all warps
        if (kp + 2 < NK2) {
            int sl = (kp + 2) % 3;   // distinct from consuming slot kp%3 and (kp+1)%3
#pragma unroll
            for (int q = 0; q < 2; q++) {
                int st = 2 * sl + q;
                load_tile(sb + st * STAGE_B,
                          Ag + (size_t)(2 * (kp + 2) + q) * KTILE, lda);
                load_tile(sb + st * STAGE_B + TILE_B,
                          Bg + (size_t)(2 * (kp + 2) + q) * KTILE, ldb);
            }
        }
        CPA_COMMIT();                // exactly one group per iteration

        int sl = kp % 3;
        consume_stage(smem + (2 * sl)     * STAGE_B, a_base, b_base, acc);
        consume_stage(smem + (2 * sl + 1) * STAGE_B, a_base, b_base, acc);
    }
}

// 4-stage single-kt mainloop (fused kernel; footprint must stay 64KB + stash)
__device__ __forceinline__ void gemm_mainloop(char* smem, uint32_t sb,
        const __half* Ag, int lda, const __half* Bg, int ldb, int NK,
        int a_base, int b_base, float acc[4][4][4]) {
#pragma unroll
    for (int mf = 0; mf < 4; mf++)
#pragma unroll
        for (int nf = 0; nf < 4; nf++)
#pragma unroll
            for (int e = 0; e < 4; e++) acc[mf][nf][e] = 0.0f;

#pragma unroll
    for (int p = 0; p < 3; p++) {
        load_tile(sb + p * STAGE_B,          Ag + p * KTILE, lda);
        load_tile(sb + p * STAGE_B + TILE_B, Bg + p * KTILE, ldb);
        CPA_COMMIT();
    }
    for (int kt = 0; kt < NK; kt++) {
        CPA_WAIT2();
        __syncthreads();
        if (kt + 3 < NK) {
            int st = (kt + 3) % STAGES;
            load_tile(sb + st * STAGE_B,          Ag + (size_t)(kt + 3) * KTILE, lda);
            load_tile(sb + st * STAGE_B + TILE_B, Bg + (size_t)(kt + 3) * KTILE, ldb);
        }
        CPA_COMMIT();
        consume_stage(smem + (kt % STAGES) * STAGE_B, a_base, b_base, acc);
    }
}

// ---------------- K2: standalone GEMM (paired mainloop) --------------------------
// ACT: 0 -> fp16 plain store (imgfeat), 1 -> gelu + fp16 permuted store (hbuf)
template <int ACT>
__global__ __launch_bounds__(256, 2)
void mma_gemm(const __half* __restrict__ A, int lda, const __half* __restrict__ Bt,
              const float* __restrict__ bias, __half* __restrict__ C,
              int Kd, int Nc) {
    extern __shared__ char smem[];
    uint32_t sb = smem_u32(smem);
    int tid = threadIdx.x, wid = tid >> 5, lane = tid & 31;
    int wm = wid & 1, wn = wid >> 1;
    int g = lane >> 2, i4 = lane & 3;
    int row0 = blockIdx.y * 128, col0 = blockIdx.x * 128;

    const int sc = 16 * (i4 ^ (g & 3));
    const int a_base = (wm * 64 + g) * ROWB + sc;
    const int b_base = (wn * 32 + g) * ROWB + sc;

    float acc[4][4][4];
    gemm_mainloop2(smem, sb, A + (size_t)row0 * lda, lda,
                   Bt + (size_t)col0 * Kd, Kd, Kd / KTILE, a_base, b_base, acc);

#pragma unroll
    for (int mf = 0; mf < 4; mf++) {
        int r_lo = row0 + wm * 64 + mf * 16 + g;
#pragma unroll
        for (int nf = 0; nf < 4; nf++) {
            int col = col0 + wn * 32 + nf * 8 + i4 * 2;
            float b0 = bias[col], b1 = bias[col + 1];
#pragma unroll
            for (int h = 0; h < 2; h++) {
                int row = r_lo + h * 8;
                float v0 = acc[mf][nf][h * 2 + 0] + b0;
                float v1 = acc[mf][nf][h * 2 + 1] + b1;
                __half2 o;
                if (ACT == 1) {
                    o.x = __float2half_rn(gelu_f(v0));
                    o.y = __float2half_rn(gelu_f(v1));
                    *(__half2*)(C + (size_t)row * Nc + permk(col)) = o;
                } else {
                    o.x = __float2half_rn(v0);
                    o.y = __float2half_rn(v1);
                    *(__half2*)(C + (size_t)row * Nc + col) = o;
                }
            }
        }
    }
}

// ---------------- K2b: fused gate-L2 + delta-L2 + final combine ------------------
__global__ __launch_bounds__(256, 2)
void fused_gd2(const __half* __restrict__ hb, const __half* __restrict__ Bg2,
               const __half* __restrict__ Bd2,
               const float* __restrict__ gbias, const float* __restrict__ dbias,
               const float* __restrict__ ptb, const int* __restrict__ pvm,
               float* __restrict__ out) {
    extern __shared__ char smem[];
    uint32_t sb = smem_u32(smem);
    __half2* stash = (__half2*)(smem + STAGES_BYTES);
    int tid = threadIdx.x, wid = tid >> 5, lane = tid & 31;
    int wm = wid & 1, wn = wid >> 1;
    int g = lane >> 2, i4 = lane & 3;
    int row0 = blockIdx.y * 128, col0 = blockIdx.x * 128;

    const int sc = 16 * (i4 ^ (g & 3));
    const int a_base = (wm * 64 + g) * ROWB + sc;
    const int b_base = (wn * 32 + g) * ROWB + sc;
    const int NK = HDim / KTILE;   // 16

    float acc[4][4][4];
    // loop 1: gate
    gemm_mainloop(smem, sb, hb + (size_t)row0 * (2 * HDim), 2 * HDim,
                  Bg2 + (size_t)col0 * HDim, HDim, NK, a_base, b_base, acc);
    // stash sigmoid(gate): 32 __half2 slots PER THREAD
    __half2* tst = stash + tid * 32;
#pragma unroll
    for (int mf = 0; mf < 4; mf++)
#pragma unroll
        for (int nf = 0; nf < 4; nf++) {
            int col = col0 + wn * 32 + nf * 8 + i4 * 2;
            float b0 = gbias[col], b1 = gbias[col + 1];
#pragma unroll
            for (int h = 0; h < 2; h++) {
                __half2 o;
                o.x = __float2half_rn(sigmoid_f(acc[mf][nf][h * 2 + 0] + b0));
                o.y = __float2half_rn(sigmoid_f(acc[mf][nf][h * 2 + 1] + b1));
                tst[(mf * 4 + nf) * 2 + h] = o;
            }
        }
    CPA_WAIT0();
    __syncthreads();   // stage buffers fully consumed before loop-2 prologue

    // loop 2: delta
    gemm_mainloop(smem, sb, hb + (size_t)row0 * (2 * HDim) + HDim, 2 * HDim,
                  Bd2 + (size_t)col0 * HDim, HDim, NK, a_base, b_base, acc);

    // epilogue: combine
#pragma unroll
    for (int mf = 0; mf < 4; mf++) {
        int r_lo = row0 + wm * 64 + mf * 16 + g;
#pragma unroll
        for (int nf = 0; nf < 4; nf++) {
            int col = col0 + wn * 32 + nf * 8 + i4 * 2;
            float b0 = dbias[col], b1 = dbias[col + 1];
#pragma unroll
            for (int h = 0; h < 2; h++) {
                int row = r_lo + h * 8;
                float v0 = acc[mf][nf][h * 2 + 0] + b0;
                float v1 = acc[mf][nf][h * 2 + 1] + b1;
                __half2 gt = tst[(mf * 4 + nf) * 2 + h];
                size_t off = (size_t)row * ODim + col;
                float2 p4 = *(const float2*)(ptb + off);
                float m = pvm[row] ? 1.0f : 0.0f;
                float o0 = (p4.x + __half2float(gt.x) * v0) * m;
                float o1 = (p4.y + __half2float(gt.y) * v1) * m;
                *(float2*)(out + off) = make_float2(o0, o1);
            }
        }
    }
}

// ---------------- K3: kNN top-3 + inverse-distance weights ----------------------
__global__ __launch_bounds__(256)
void knn_kernel(const float* __restrict__ pc, const float* __restrict__ ic,
                const int* __restrict__ imask,
                int* __restrict__ knn_idx, float* __restrict__ knn_w) {
    __shared__ float4 cs[Mm];
    int b = blockIdx.x;
    const float INFV = __int_as_float(0x7f800000);
    for (int m = threadIdx.x; m < Mm; m += 256) {
        size_t ci = ((size_t)b * Mm + m) * 3;
        float x = ic[ci], y = ic[ci + 1], z = ic[ci + 2];
        float s2 = imask[b * Mm + m] ? (x * x + y * y + z * z) : INFV;
        cs[m] = make_float4(x, y, z, s2);
    }
    __syncthreads();

    int n = blockIdx.y * 256 + threadIdx.x;
    size_t pidx = (size_t)b * Nn + n;
    float qx = pc[pidx * 3], qy = pc[pidx * 3 + 1], qz = pc[pidx * 3 + 2];
    float q2 = qx * qx + qy * qy + qz * qz;

    float d0 = INFV, d1 = INFV, d2v = INFV;
    int j0 = 0, j1 = 0, j2 = 0;
#pragma unroll 4
    for (int m = 0; m < Mm; m++) {
        float4 c = cs[m];
        float d = fmaxf(q2 + c.w - 2.0f * (qx * c.x + qy * c.y + qz * c.z), 0.0f);
        if (d < d2v) {
            if (d < d1) {
                d2v = d1; j2 = j1;
                if (d < d0) { d1 = d0; j1 = j0; d0 = d; j0 = m; }
                else        { d1 = d;  j1 = m; }
            } else { d2v = d; j2 = m; }
        }
    }
    float w0 = 1.0f / fmaxf(sqrtf(d0),  1e-6f);
    float w1 = 1.0f / fmaxf(sqrtf(d1),  1e-6f);
    float w2 = 1.0f / fmaxf(sqrtf(d2v), 1e-6f);
    float inv = 1.0f / fmaxf(w0 + w1 + w2, 1e-6f);
    size_t base = pidx * 3;
    knn_idx[base + 0] = b * Mm + j0;
    knn_idx[base + 1] = b * Mm + j1;
    knn_idx[base + 2] = b * Mm + j2;
    knn_w[base + 0] = w0 * inv;
    knn_w[base + 1] = w1 * inv;
    knn_w[base + 2] = w2 * inv;
}

// ---------------- K4: gather (fp16 imgfeat) + concat + LN, fp16 permuted --------
__global__ __launch_bounds__(128)
void fin_ln_kernel(const float* __restrict__ pt, const int* __restrict__ pvm,
                   __half* __restrict__ out) {
    int p = blockIdx.x, tid = threadIdx.x;
    float4 v;
    if (tid < 64) {
        v = *(const float4*)&pt[(size_t)p * ODim + tid * 4];
    } else {
        int base = p * 3;
        int i0 = g_knn_idx[base], i1 = g_knn_idx[base + 1], i2 = g_knn_idx[base + 2];
        float w0 = g_knn_w[base], w1 = g_knn_w[base + 1], w2 = g_knn_w[base + 2];
        int o = (tid - 64) * 4;
        __half2 a0 = *(const __half2*)&g_imgfeat[(size_t)i0 * ODim + o];
        __half2 a1 = *(const __half2*)&g_imgfeat[(size_t)i0 * ODim + o + 2];
        __half2 b0 = *(const __half2*)&g_imgfeat[(size_t)i1 * ODim + o];
        __half2 b1 = *(const __half2*)&g_imgfeat[(size_t)i1 * ODim + o + 2];
        __half2 c0 = *(const __half2*)&g_imgfeat[(size_t)i2 * ODim + o];
        __half2 c1 = *(const __half2*)&g_imgfeat[(size_t)i2 * ODim + o + 2];
        float pv = pvm[p] ? 1.0f : 0.0f;
        v.x = (w0 * __half2float(a0.x) + w1 * __half2float(b0.x) + w2 * __half2float(c0.x)) * pv;
        v.y = (w0 * __half2float(a0.y) + w1 * __half2float(b0.y) + w2 * __half2float(c0.y)) * pv;
        v.z = (w0 * __half2float(a1.x) + w1 * __half2float(b1.x) + w2 * __half2float(c1.x)) * pv;
        v.w = (w0 * __half2float(a1.y) + w1 * __half2float(b1.y) + w2 * __half2float(c1.y)) * pv;
    }
    float s  = v.x + v.y + v.z + v.w;
    float ss = v.x * v.x + v.y * v.y + v.z * v.z + v.w * v.w;
    float2 r = block_reduce2(s, ss);
    float mean = r.x * (1.0f / 512.0f);
    float var  = fmaxf(r.y * (1.0f / 512.0f) - mean * mean, 0.0f);
    float rstd = rsqrtf(var + 1e-5f);
    __half* orow = out + (size_t)p * 512;
    int c = tid * 4;
    __half2 o01, o23;
    o01.x = __float2half_rn((v.x - mean) * rstd);
    o01.y = __float2half_rn((v.y - mean) * rstd);
    o23.x = __float2half_rn((v.z - mean) * rstd);
    o23.y = __float2half_rn((v.w - mean) * rstd);
    *(__half2*)(orow + permk(c))     = o01;
    *(__half2*)(orow + permk(c + 2)) = o23;
}

// ---------------- launch ---------------------------------------------------------
extern "C" void kernel_launch(void* const* d_in, const int* in_sizes, int n_in,
                              void* d_out, int out_size) {
    const float* pt      = (const float*)d_in[0];
    const float* pc      = (const float*)d_in[1];
    const float* it      = (const float*)d_in[2];
    const float* icd     = (const float*)d_in[3];
    const int*   pvm     = (const int*)d_in[4];
    const int*   ivm     = (const int*)d_in[5];
    const float* ip_ln_g = (const float*)d_in[6];
    const float* ip_ln_b = (const float*)d_in[7];
    const float* ip_w1   = (const float*)d_in[8];
    const float* ip_b1   = (const float*)d_in[9];
    const float* ip_w2   = (const float*)d_in[10];
    const float* ip_b2   = (const float*)d_in[11];
    const float* g_ln_g  = (const float*)d_in[12];
    const float* g_ln_b  = (const float*)d_in[13];
    const float* g_w1    = (const float*)d_in[14];
    const float* g_b1    = (const float*)d_in[15];
    const float* g_w2    = (const float*)d_in[16];
    const float* g_b2    = (const float*)d_in[17];
    const float* d_ln_g  = (const float*)d_in[18];
    const float* d_ln_b  = (const float*)d_in[19];
    const float* d_w1    = (const float*)d_in[20];
    const float* d_b1    = (const float*)d_in[21];
    const float* d_w2    = (const float*)d_in[22];
    const float* d_b2    = (const float*)d_in[23];
    float* out = (float*)d_out;

    __half *xln, *hbuf, *imgf, *finln, *wt_ip1, *wt_gd1, *wt_ip2, *wt_g2, *wt_d2;
    float *knnw, *bpip, *bpgd;
    int* knni;
    cudaGetSymbolAddress((void**)&xln,    g_xln);
    cudaGetSymbolAddress((void**)&hbuf,   g_hbuf);
    cudaGetSymbolAddress((void**)&imgf,   g_imgfeat);
    cudaGetSymbolAddress((void**)&finln,  g_finln);
    cudaGetSymbolAddress((void**)&knni,   g_knn_idx);
    cudaGetSymbolAddress((void**)&knnw,   g_knn_w);
    cudaGetSymbolAddress((void**)&wt_ip1, g_wt_ip1);
    cudaGetSymbolAddress((void**)&wt_gd1, g_wt_gd1);
    cudaGetSymbolAddress((void**)&wt_ip2, g_wt_ip2);
    cudaGetSymbolAddress((void**)&wt_g2,  g_wt_g2);
    cudaGetSymbolAddress((void**)&wt_d2,  g_wt_d2);
    cudaGetSymbolAddress((void**)&bpip,   g_bp_ip);
    cudaGetSymbolAddress((void**)&bpgd,   g_bp_gd);

    cudaFuncSetAttribute(mma_gemm<0>, cudaFuncAttributeMaxDynamicSharedMemorySize, SM_GEMM);
    cudaFuncSetAttribute(mma_gemm<1>, cudaFuncAttributeMaxDynamicSharedMemorySize, SM_GEMM);
    cudaFuncSetAttribute(fused_gd2,  cudaFuncAttributeMaxDynamicSharedMemorySize, SM_FUSED);

    // ncu captures 0-based launch index 3 -> keep the img L1 GEMM there.
    fold_w1<<<(IDim * HDim + 255) / 256, 256>>>(ip_w1, ip_ln_g, wt_ip1, IDim, HDim);    // 0
    fold_b1<<<HDim / 64, 256>>>(ip_w1, ip_ln_b, ip_b1, bpip, IDim, HDim);               // 1
    ln_img_kernel<<<ROWS_IMG, 256>>>(it, xln);                                          // 2

    // 3: image MLP layer 1 (PROFILED launch)
    mma_gemm<1><<<dim3(HDim / 128, ROWS_IMG / 128), 256, SM_GEMM>>>(
        xln, IDim, wt_ip1, bpip, hbuf, IDim, HDim);

    transpose_k<<<(HDim * ODim + 255) / 256, 256>>>(ip_w2, wt_ip2, HDim, ODim);         // 4
    // 5: image MLP layer 2 -> imgfeat (fp16 plain)
    mma_gemm<0><<<dim3(ODim / 128, ROWS_IMG / 128), 256, SM_GEMM>>>(
        hbuf, HDim, wt_ip2, ip_b2, imgf, HDim, ODim);

    // remaining prep
    fold_w1<<<(HDim * HDim + 255) / 256, 256>>>(g_w1, g_ln_g, wt_gd1, HDim, HDim);      // 6
    fold_w1<<<(HDim * HDim + 255) / 256, 256>>>(d_w1, d_ln_g, wt_gd1 + (size_t)HDim * HDim,
                                                HDim, HDim);                            // 7
    fold_b1<<<HDim / 64, 256>>>(g_w1, g_ln_b, g_b1, bpgd, HDim, HDim);                  // 8
    fold_b1<<<HDim / 64, 256>>>(d_w1, d_ln_b, d_b1, bpgd + HDim, HDim, HDim);           // 9
    transpose_k<<<(HDim * ODim + 255) / 256, 256>>>(g_w2, wt_g2, HDim, ODim);           // 10
    transpose_k<<<(HDim * ODim + 255) / 256, 256>>>(d_w2, wt_d2, HDim, ODim);           // 11

    knn_kernel<<<dim3(Bb, Nn / 256), 256>>>(pc, icd, ivm, knni, knnw);                  // 12
    fin_ln_kernel<<<ROWS_PT, 128>>>(pt, pvm, finln);                                    // 13

    // 14: fused gate|delta layer 1 -> hbuf [ROWS_PT, 1024]
    mma_gemm<1><<<dim3((2 * HDim) / 128, ROWS_PT / 128), 256, SM_GEMM>>>(
        finln, 2 * ODim, wt_gd1, bpgd, hbuf, 2 * ODim, 2 * HDim);

    // 15: fused gate-L2 + delta-L2 + combine -> out
    fused_gd2<<<dim3(ODim / 128, ROWS_PT / 128), 256, SM_FUSED>>>(
        hbuf, wt_g2, wt_d2, g_b2, d_b2, pt, pvm, out);
}

// round 14
// speedup vs baseline: 1.1038x; 1.0692x over previous
#include <cuda_runtime.h>
#include <cuda_fp16.h>
#include <math.h>
#include <stdint.h>

// Problem dims (fixed by the dataset)
#define Bb   16
#define Nn   4096
#define Mm   1024
#define IDim 768
#define HDim 512
#define ODim 256
#define ROWS_IMG (Bb*Mm)   // 16384
#define ROWS_PT  (Bb*Nn)   // 65536

// ---------------- scratch (device globals; no allocation allowed) -------------
__device__ __align__(16) __half g_xln[ROWS_IMG * IDim];          // LN img tokens (fp16, permuted)
__device__ __align__(16) __half g_hbuf[ROWS_PT * 2 * HDim];      // hidden (fp16, permuted)
__device__ __align__(16) __half g_imgfeat[ROWS_IMG * ODim];      // image MLP out (fp16 plain)
__device__ __align__(16) __half g_finln[ROWS_PT * (2 * ODim)];   // fin̂ (fp16, permuted)
__device__ int   g_knn_idx[ROWS_PT * 3];
__device__ float g_knn_w[ROWS_PT * 3];
// transposed (LN-folded) weights: [N,K] K-major, fp16, permuted
__device__ __align__(16) __half g_wt_ip1[HDim * IDim];
__device__ __align__(16) __half g_wt_gd1[(2 * HDim) * HDim];     // fused gate|delta layer-1
__device__ __align__(16) __half g_wt_ip2[ODim * HDim];
__device__ __align__(16) __half g_wt_g2[ODim * HDim];
__device__ __align__(16) __half g_wt_d2[ODim * HDim];
__device__ float g_bp_ip[HDim];
__device__ float g_bp_gd[2 * HDim];                              // fused gate|delta bias

// ---------------- helpers ------------------------------------------------------
// 32-wide k permutation: both 16-k steps of a 32-k tile land in one 16B chunk.
__device__ __host__ __forceinline__ int permk(int k) {
    return (k & ~31) | (((k >> 1) & 3) << 3) | (((k >> 4) & 1) << 2)
         | (((k >> 3) & 1) << 1) | (k & 1);
}
__device__ __forceinline__ float gelu_f(float x) {
    return 0.5f * x * (1.0f + erff(x * 0.70710678118654752f));
}
__device__ __forceinline__ float sigmoid_f(float x) {
    return 1.0f / (1.0f + __expf(-x));
}
__device__ __forceinline__ float2 block_reduce2(float s, float ss) {
    __shared__ float sh[64];
    int lane = threadIdx.x & 31, w = threadIdx.x >> 5;
#pragma unroll
    for (int o = 16; o; o >>= 1) {
        s  += __shfl_down_sync(0xffffffffu, s,  o);
        ss += __shfl_down_sync(0xffffffffu, ss, o);
    }
    if (lane == 0) { sh[w] = s; sh[32 + w] = ss; }
    __syncthreads();
    int nw = (blockDim.x + 31) >> 5;
    if (w == 0) {
        s  = (lane < nw) ? sh[lane]      : 0.0f;
        ss = (lane < nw) ? sh[32 + lane] : 0.0f;
#pragma unroll
        for (int o = 16; o; o >>= 1) {
            s  += __shfl_down_sync(0xffffffffu, s,  o);
            ss += __shfl_down_sync(0xffffffffu, ss, o);
        }
        if (lane == 0) { sh[0] = s; sh[32] = ss; }
    }
    __syncthreads();
    return make_float2(sh[0], sh[32]);
}

// ---------------- K0a: ALL weight folds/transposes in ONE kernel ----------------
// segments (256-thread blocks over 1,310,720 elements):
//  [0, 393216)        fold ip_w1 (768x512)  -> g_wt_ip1
//  [393216, 655360)   fold g_w1  (512x512)  -> g_wt_gd1[:512]
//  [655360, 917504)   fold d_w1  (512x512)  -> g_wt_gd1[512:]
//  [917504, 1048576)  transpose ip_w2 (512x256) -> g_wt_ip2
//  [1048576, 1179648) transpose g_w2  -> g_wt_g2
//  [1179648, 1310720) transpose d_w2  -> g_wt_d2
#define PREP_TOTAL 1310720
__global__ void prep_weights(const float* __restrict__ ip_w1, const float* __restrict__ ip_g,
                             const float* __restrict__ gw1, const float* __restrict__ gg,
                             const float* __restrict__ dw1, const float* __restrict__ dg,
                             const float* __restrict__ ip_w2, const float* __restrict__ gw2,
                             const float* __restrict__ dw2) {
    int idx = blockIdx.x * blockDim.x + threadIdx.x;
    if (idx < 393216) {
        int k = idx / HDim, n = idx % HDim;
        g_wt_ip1[(size_t)n * IDim + permk(k)] = __float2half_rn(ip_g[k] * ip_w1[idx]);
    } else if (idx < 655360) {
        int e = idx - 393216;
        int k = e / HDim, n = e % HDim;
        g_wt_gd1[(size_t)n * HDim + permk(k)] = __float2half_rn(gg[k] * gw1[e]);
    } else if (idx < 917504) {
        int e = idx - 655360;
        int k = e / HDim, n = e % HDim;
        g_wt_gd1[(size_t)(n + HDim) * HDim + permk(k)] = __float2half_rn(dg[k] * dw1[e]);
    } else if (idx < 1048576) {
        int e = idx - 917504;
        int k = e / ODim, n = e % ODim;
        g_wt_ip2[(size_t)n * HDim + permk(k)] = __float2half_rn(ip_w2[e]);
    } else if (idx < 1179648) {
        int e = idx - 1048576;
        int k = e / ODim, n = e % ODim;
        g_wt_g2[(size_t)n * HDim + permk(k)] = __float2half_rn(gw2[e]);
    } else if (idx < PREP_TOTAL) {
        int e = idx - 1179648;
        int k = e / ODim, n = e % ODim;
        g_wt_d2[(size_t)n * HDim + permk(k)] = __float2half_rn(dw2[e]);
    }
}

// ---------------- K0b: all 3 bias folds in ONE kernel (blockIdx.y selects) ------
__global__ void prep_bias(const float* __restrict__ ip_w1, const float* __restrict__ ip_bln,
                          const float* __restrict__ ip_b1,
                          const float* __restrict__ gw1, const float* __restrict__ g_bln,
                          const float* __restrict__ g_b1,
                          const float* __restrict__ dw1, const float* __restrict__ d_bln,
                          const float* __restrict__ d_b1) {
    __shared__ float sh[256];
    const float *W, *bln, *b1;
    float* outp;
    int Kd;
    if (blockIdx.y == 0)      { W = ip_w1; bln = ip_bln; b1 = ip_b1; outp = g_bp_ip;        Kd = IDim; }
    else if (blockIdx.y == 1) { W = gw1;   bln = g_bln;  b1 = g_b1;  outp = g_bp_gd;        Kd = HDim; }
    else                      { W = dw1;   bln = d_bln;  b1 = d_b1;  outp = g_bp_gd + HDim; Kd = HDim; }
    int nl = threadIdx.x & 63, ks = threadIdx.x >> 6;
    int n = blockIdx.x * 64 + nl;
    float acc = 0.0f;
    for (int k = ks; k < Kd; k += 4)
        acc += bln[k] * W[(size_t)k * HDim + n];
    sh[threadIdx.x] = acc;
    __syncthreads();
    if (ks == 0)
        outp[n] = b1[n] + sh[nl] + sh[64 + nl] + sh[128 + nl] + sh[192 + nl];
}

// ---------------- K1: LN (normalize only), fp16 permuted store ------------------
__global__ void ln_img_kernel(const float* __restrict__ x, __half* __restrict__ y) {
    int row = blockIdx.x, tid = threadIdx.x;
    const float* xr = x + (size_t)row * IDim;
    float v0 = xr[tid], v1 = xr[tid + 256], v2 = xr[tid + 512];
    float s = v0 + v1 + v2;
    float ss = v0 * v0 + v1 * v1 + v2 * v2;
    float2 r = block_reduce2(s, ss);
    float mean = r.x * (1.0f / 768.0f);
    float var  = fmaxf(r.y * (1.0f / 768.0f) - mean * mean, 0.0f);
    float rstd = rsqrtf(var + 1e-5f);
    __half* yr = y + (size_t)row * IDim;
    yr[permk(tid)]       = __float2half_rn((v0 - mean) * rstd);
    yr[permk(tid + 256)] = __float2half_rn((v1 - mean) * rstd);
    yr[permk(tid + 512)] = __float2half_rn((v2 - mean) * rstd);
}

// ---------------- GEMM core: fp16 m16n8k16 mma.sync -----------------------------
#define KTILE   32
#define ROWB    64                           // bytes/row, XOR swizzle (no pad)
#define TILE_B  (128 * ROWB)                 // 8192 bytes
#define STAGE_B (2 * TILE_B)                 // 16384
#define STAGES  4
#define STAGES_BYTES (STAGES * STAGE_B)      // 65536
#define GSTASH_BYTES (256 * 32 * 4)          // 32768: 32 __half2 per thread
#define SM_GEMM  STAGES_BYTES
#define SM_FUSED (STAGES_BYTES + GSTASH_BYTES)

#define CPA_COMMIT() asm volatile("cp.async.commit_group;" ::: "memory")
#define CPA_WAIT2()  asm volatile("cp.async.wait_group 2;" ::: "memory")
#define CPA_WAIT0()  asm volatile("cp.async.wait_group 0;" ::: "memory")

__device__ __forceinline__ uint32_t smem_u32(const void* p) {
    uint32_t a;
    asm("{ .reg .u64 t; cvta.to.shared.u64 t, %1; cvt.u32.u64 %0, t; }" : "=r"(a) : "l"(p));
    return a;
}
__device__ __forceinline__ void cpa16(uint32_t so, const __half* gp) {
    asm volatile("cp.async.cg.shared.global [%0], [%1], 16;" :: "r"(so), "l"(gp));
}

__device__ __forceinline__ void mma_f16(float* d, uint32_t a0, uint32_t a1, uint32_t a2,
                                        uint32_t a3, uint32_t b0, uint32_t b1) {
    asm volatile(
        "mma.sync.aligned.m16n8k16.row.col.f32.f16.f16.f32 "
        "{%0,%1,%2,%3}, {%4,%5,%6,%7}, {%8,%9}, {%0,%1,%2,%3};"
        : "+f"(d[0]), "+f"(d[1]), "+f"(d[2]), "+f"(d[3])
        : "r"(a0), "r"(a1), "r"(a2), "r"(a3), "r"(b0), "r"(b1));
}

// consume one 32-k stage: 12 x LDS.128 + 32 MMAs
__device__ __forceinline__ void consume_stage(const char* smem_stage,
        int a_base, int b_base, float acc[4][4][4]) {
    const char* As = smem_stage + a_base;
    const char* Bs = smem_stage + TILE_B + b_base;
    uint4 af[8], bq[4];
#pragma unroll
    for (int mf = 0; mf < 4; mf++) {
        af[2 * mf]     = *(const uint4*)(As + mf * (16 * ROWB));
        af[2 * mf + 1] = *(const uint4*)(As + mf * (16 * ROWB) + 8 * ROWB);
    }
#pragma unroll
    for (int nf = 0; nf < 4; nf++)
        bq[nf] = *(const uint4*)(Bs + nf * (8 * ROWB));
#pragma unroll
    for (int mf = 0; mf < 4; mf++)
#pragma unroll
        for (int nf = 0; nf < 4; nf++) {
            mma_f16(acc[mf][nf],
                    af[2 * mf].x, af[2 * mf + 1].x, af[2 * mf].y, af[2 * mf + 1].y,
                    bq[nf].x, bq[nf].y);
            mma_f16(acc[mf][nf],
                    af[2 * mf].z, af[2 * mf + 1].z, af[2 * mf].w, af[2 * mf + 1].w,
                    bq[nf].z, bq[nf].w);
        }
}

// 4-stage mainloop, unrolled by 4: compile-time stage indices, precomputed
// per-thread cp.async offsets, pointer-increment addressing. Requires NK % 4 == 0.
__device__ __forceinline__ void gemm_mainloop(char* smem, uint32_t sb,
        const __half* Ag, int lda, const __half* Bg, int ldb, int NK,
        int a_base, int b_base, float acc[4][4][4]) {
#pragma unroll
    for (int mf = 0; mf < 4; mf++)
#pragma unroll
        for (int nf = 0; nf < 4; nf++)
#pragma unroll
            for (int e = 0; e < 4; e++) acc[mf][nf][e] = 0.0f;

    // precompute per-thread copy offsets (2 chunks of 16B per tile per thread)
    int t = threadIdx.x;
    int r0 = t >> 2, c0 = t & 3;
    int r1 = (t + 256) >> 2, c1 = (t + 256) & 3;
    uint32_t so0 = (uint32_t)(r0 * ROWB + 16 * (c0 ^ (r0 & 3)));
    uint32_t so1 = (uint32_t)(r1 * ROWB + 16 * (c1 ^ (r1 & 3)));
    size_t gA0 = (size_t)r0 * lda + c0 * 8, gA1 = (size_t)r1 * lda + c1 * 8;
    size_t gB0 = (size_t)r0 * ldb + c0 * 8, gB1 = (size_t)r1 * ldb + c1 * 8;

    const __half* Ap = Ag;
    const __half* Bp = Bg;
    // prologue: stages 0,1,2
#pragma unroll
    for (int p = 0; p < 3; p++) {
        uint32_t sA = sb + p * STAGE_B, sB = sA + TILE_B;
        cpa16(sA + so0, Ap + gA0); cpa16(sA + so1, Ap + gA1);
        cpa16(sB + so0, Bp + gB0); cpa16(sB + so1, Bp + gB1);
        CPA_COMMIT();
        Ap += KTILE; Bp += KTILE;
    }
    for (int kt = 0; kt < NK; kt += 4) {
#pragma unroll
        for (int u = 0; u < 4; u++) {
            CPA_WAIT2();
            __syncthreads();
            if (kt + u + 3 < NK) {
                const int st = (u + 3) & 3;            // compile-time
                uint32_t sA = sb + st * STAGE_B, sB = sA + TILE_B;
                cpa16(sA + so0, Ap + gA0); cpa16(sA + so1, Ap + gA1);
                cpa16(sB + so0, Bp + gB0); cpa16(sB + so1, Bp + gB1);
                Ap += KTILE; Bp += KTILE;
            }
            CPA_COMMIT();
            consume_stage(smem + u * STAGE_B, a_base, b_base, acc);  // u compile-time
        }
    }
}

// ---------------- K2: standalone GEMM --------------------------------------------
// ACT: 0 -> fp16 plain store (imgfeat), 1 -> gelu + fp16 permuted store (hbuf)
template <int ACT>
__global__ __launch_bounds__(256, 2)
void mma_gemm(const __half* __restrict__ A, int lda, const __half* __restrict__ Bt,
              const float* __restrict__ bias, __half* __restrict__ C,
              int Kd, int Nc) {
    extern __shared__ char smem[];
    uint32_t sb = smem_u32(smem);
    int tid = threadIdx.x, wid = tid >> 5, lane = tid & 31;
    int wm = wid & 1, wn = wid >> 1;
    int g = lane >> 2, i4 = lane & 3;
    int row0 = blockIdx.y * 128, col0 = blockIdx.x * 128;

    const int sc = 16 * (i4 ^ (g & 3));
    const int a_base = (wm * 64 + g) * ROWB + sc;
    const int b_base = (wn * 32 + g) * ROWB + sc;

    float acc[4][4][4];
    gemm_mainloop(smem, sb, A + (size_t)row0 * lda, lda,
                  Bt + (size_t)col0 * Kd, Kd, Kd / KTILE, a_base, b_base, acc);

#pragma unroll
    for (int mf = 0; mf < 4; mf++) {
        int r_lo = row0 + wm * 64 + mf * 16 + g;
#pragma unroll
        for (int nf = 0; nf < 4; nf++) {
            int col = col0 + wn * 32 + nf * 8 + i4 * 2;
            float b0 = bias[col], b1 = bias[col + 1];
#pragma unroll
            for (int h = 0; h < 2; h++) {
                int row = r_lo + h * 8;
                float v0 = acc[mf][nf][h * 2 + 0] + b0;
                float v1 = acc[mf][nf][h * 2 + 1] + b1;
                __half2 o;
                if (ACT == 1) {
                    o.x = __float2half_rn(gelu_f(v0));
                    o.y = __float2half_rn(gelu_f(v1));
                    *(__half2*)(C + (size_t)row * Nc + permk(col)) = o;
                } else {
                    o.x = __float2half_rn(v0);
                    o.y = __float2half_rn(v1);
                    *(__half2*)(C + (size_t)row * Nc + col) = o;
                }
            }
        }
    }
}

// ---------------- K2b: fused gate-L2 + delta-L2 + final combine ------------------
__global__ __launch_bounds__(256, 2)
void fused_gd2(const __half* __restrict__ hb, const __half* __restrict__ Bg2,
               const __half* __restrict__ Bd2,
               const float* __restrict__ gbias, const float* __restrict__ dbias,
               const float* __restrict__ ptb, const int* __restrict__ pvm,
               float* __restrict__ out) {
    extern __shared__ char smem[];
    uint32_t sb = smem_u32(smem);
    __half2* stash = (__half2*)(smem + STAGES_BYTES);
    int tid = threadIdx.x, wid = tid >> 5, lane = tid & 31;
    int wm = wid & 1, wn = wid >> 1;
    int g = lane >> 2, i4 = lane & 3;
    int row0 = blockIdx.y * 128, col0 = blockIdx.x * 128;

    const int sc = 16 * (i4 ^ (g & 3));
    const int a_base = (wm * 64 + g) * ROWB + sc;
    const int b_base = (wn * 32 + g) * ROWB + sc;
    const int NK = HDim / KTILE;   // 16

    float acc[4][4][4];
    // loop 1: gate
    gemm_mainloop(smem, sb, hb + (size_t)row0 * (2 * HDim), 2 * HDim,
                  Bg2 + (size_t)col0 * HDim, HDim, NK, a_base, b_base, acc);
    // stash sigmoid(gate): 32 __half2 slots PER THREAD
    __half2* tst = stash + tid * 32;
#pragma unroll
    for (int mf = 0; mf < 4; mf++)
#pragma unroll
        for (int nf = 0; nf < 4; nf++) {
            int col = col0 + wn * 32 + nf * 8 + i4 * 2;
            float b0 = gbias[col], b1 = gbias[col + 1];
#pragma unroll
            for (int h = 0; h < 2; h++) {
                __half2 o;
                o.x = __float2half_rn(sigmoid_f(acc[mf][nf][h * 2 + 0] + b0));
                o.y = __float2half_rn(sigmoid_f(acc[mf][nf][h * 2 + 1] + b1));
                tst[(mf * 4 + nf) * 2 + h] = o;
            }
        }
    CPA_WAIT0();
    __syncthreads();   // stage buffers fully consumed before loop-2 prologue

    // loop 2: delta
    gemm_mainloop(smem, sb, hb + (size_t)row0 * (2 * HDim) + HDim, 2 * HDim,
                  Bd2 + (size_t)col0 * HDim, HDim, NK, a_base, b_base, acc);

    // epilogue: combine
#pragma unroll
    for (int mf = 0; mf < 4; mf++) {
        int r_lo = row0 + wm * 64 + mf * 16 + g;
#pragma unroll
        for (int nf = 0; nf < 4; nf++) {
            int col = col0 + wn * 32 + nf * 8 + i4 * 2;
            float b0 = dbias[col], b1 = dbias[col + 1];
#pragma unroll
            for (int h = 0; h < 2; h++) {
                int row = r_lo + h * 8;
                float v0 = acc[mf][nf][h * 2 + 0] + b0;
                float v1 = acc[mf][nf][h * 2 + 1] + b1;
                __half2 gt = tst[(mf * 4 + nf) * 2 + h];
                size_t off = (size_t)row * ODim + col;
                float2 p4 = *(const float2*)(ptb + off);
                float m = pvm[row] ? 1.0f : 0.0f;
                float o0 = (p4.x + __half2float(gt.x) * v0) * m;
                float o1 = (p4.y + __half2float(gt.y) * v1) * m;
                *(float2*)(out + off) = make_float2(o0, o1);
            }
        }
    }
}

// ---------------- K3: kNN top-3 + inverse-distance weights ----------------------
__global__ __launch_bounds__(256)
void knn_kernel(const float* __restrict__ pc, const float* __restrict__ ic,
                const int* __restrict__ imask,
                int* __restrict__ knn_idx, float* __restrict__ knn_w) {
    __shared__ float4 cs[Mm];
    int b = blockIdx.x;
    const float INFV = __int_as_float(0x7f800000);
    for (int m = threadIdx.x; m < Mm; m += 256) {
        size_t ci = ((size_t)b * Mm + m) * 3;
        float x = ic[ci], y = ic[ci + 1], z = ic[ci + 2];
        float s2 = imask[b * Mm + m] ? (x * x + y * y + z * z) : INFV;
        cs[m] = make_float4(x, y, z, s2);
    }
    __syncthreads();

    int n = blockIdx.y * 256 + threadIdx.x;
    size_t pidx = (size_t)b * Nn + n;
    float qx = pc[pidx * 3], qy = pc[pidx * 3 + 1], qz = pc[pidx * 3 + 2];
    float q2 = qx * qx + qy * qy + qz * qz;

    float d0 = INFV, d1 = INFV, d2v = INFV;
    int j0 = 0, j1 = 0, j2 = 0;
#pragma unroll 4
    for (int m = 0; m < Mm; m++) {
        float4 c = cs[m];
        float d = fmaxf(q2 + c.w - 2.0f * (qx * c.x + qy * c.y + qz * c.z), 0.0f);
        if (d < d2v) {
            if (d < d1) {
                d2v = d1; j2 = j1;
                if (d < d0) { d1 = d0; j1 = j0; d0 = d; j0 = m; }
                else        { d1 = d;  j1 = m; }
            } else { d2v = d; j2 = m; }
        }
    }
    float w0 = 1.0f / fmaxf(sqrtf(d0),  1e-6f);
    float w1 = 1.0f / fmaxf(sqrtf(d1),  1e-6f);
    float w2 = 1.0f / fmaxf(sqrtf(d2v), 1e-6f);
    float inv = 1.0f / fmaxf(w0 + w1 + w2, 1e-6f);
    size_t base = pidx * 3;
    knn_idx[base + 0] = b * Mm + j0;
    knn_idx[base + 1] = b * Mm + j1;
    knn_idx[base + 2] = b * Mm + j2;
    knn_w[base + 0] = w0 * inv;
    knn_w[base + 1] = w1 * inv;
    knn_w[base + 2] = w2 * inv;
}

// ---------------- K4: gather (fp16 imgfeat) + concat + LN, fp16 permuted --------
__global__ __launch_bounds__(128)
void fin_ln_kernel(const float* __restrict__ pt, const int* __restrict__ pvm,
                   __half* __restrict__ out) {
    int p = blockIdx.x, tid = threadIdx.x;
    float4 v;
    if (tid < 64) {
        v = *(const float4*)&pt[(size_t)p * ODim + tid * 4];
    } else {
        int base = p * 3;
        int i0 = g_knn_idx[base], i1 = g_knn_idx[base + 1], i2 = g_knn_idx[base + 2];
        float w0 = g_knn_w[base], w1 = g_knn_w[base + 1], w2 = g_knn_w[base + 2];
        int o = (tid - 64) * 4;
        __half2 a0 = *(const __half2*)&g_imgfeat[(size_t)i0 * ODim + o];
        __half2 a1 = *(const __half2*)&g_imgfeat[(size_t)i0 * ODim + o + 2];
        __half2 b0 = *(const __half2*)&g_imgfeat[(size_t)i1 * ODim + o];
        __half2 b1 = *(const __half2*)&g_imgfeat[(size_t)i1 * ODim + o + 2];
        __half2 c0 = *(const __half2*)&g_imgfeat[(size_t)i2 * ODim + o];
        __half2 c1 = *(const __half2*)&g_imgfeat[(size_t)i2 * ODim + o + 2];
        float pv = pvm[p] ? 1.0f : 0.0f;
        v.x = (w0 * __half2float(a0.x) + w1 * __half2float(b0.x) + w2 * __half2float(c0.x)) * pv;
        v.y = (w0 * __half2float(a0.y) + w1 * __half2float(b0.y) + w2 * __half2float(c0.y)) * pv;
        v.z = (w0 * __half2float(a1.x) + w1 * __half2float(b1.x) + w2 * __half2float(c1.x)) * pv;
        v.w = (w0 * __half2float(a1.y) + w1 * __half2float(b1.y) + w2 * __half2float(c1.y)) * pv;
    }
    float s  = v.x + v.y + v.z + v.w;
    float ss = v.x * v.x + v.y * v.y + v.z * v.z + v.w * v.w;
    float2 r = block_reduce2(s, ss);
    float mean = r.x * (1.0f / 512.0f);
    float var  = fmaxf(r.y * (1.0f / 512.0f) - mean * mean, 0.0f);
    float rstd = rsqrtf(var + 1e-5f);
    __half* orow = out + (size_t)p * 512;
    int c = tid * 4;
    __half2 o01, o23;
    o01.x = __float2half_rn((v.x - mean) * rstd);
    o01.y = __float2half_rn((v.y - mean) * rstd);
    o23.x = __float2half_rn((v.z - mean) * rstd);
    o23.y = __float2half_rn((v.w - mean) * rstd);
    *(__half2*)(orow + permk(c))     = o01;
    *(__half2*)(orow + permk(c + 2)) = o23;
}

// ---------------- launch ---------------------------------------------------------
extern "C" void kernel_launch(void* const* d_in, const int* in_sizes, int n_in,
                              void* d_out, int out_size) {
    const float* pt      = (const float*)d_in[0];
    const float* pc      = (const float*)d_in[1];
    const float* it      = (const float*)d_in[2];
    const float* icd     = (const float*)d_in[3];
    const int*   pvm     = (const int*)d_in[4];
    const int*   ivm     = (const int*)d_in[5];
    const float* ip_ln_g = (const float*)d_in[6];
    const float* ip_ln_b = (const float*)d_in[7];
    const float* ip_w1   = (const float*)d_in[8];
    const float* ip_b1   = (const float*)d_in[9];
    const float* ip_w2   = (const float*)d_in[10];
    const float* ip_b2   = (const float*)d_in[11];
    const float* g_ln_g  = (const float*)d_in[12];
    const float* g_ln_b  = (const float*)d_in[13];
    const float* g_w1    = (const float*)d_in[14];
    const float* g_b1    = (const float*)d_in[15];
    const float* g_w2    = (const float*)d_in[16];
    const float* g_b2    = (const float*)d_in[17];
    const float* d_ln_g  = (const float*)d_in[18];
    const float* d_ln_b  = (const float*)d_in[19];
    const float* d_w1    = (const float*)d_in[20];
    const float* d_b1    = (const float*)d_in[21];
    const float* d_w2    = (const float*)d_in[22];
    const float* d_b2    = (const float*)d_in[23];
    float* out = (float*)d_out;

    __half *xln, *hbuf, *imgf, *finln, *wt_ip1, *wt_gd1, *wt_ip2, *wt_g2, *wt_d2;
    float *knnw, *bpip, *bpgd;
    int* knni;
    cudaGetSymbolAddress((void**)&xln,    g_xln);
    cudaGetSymbolAddress((void**)&hbuf,   g_hbuf);
    cudaGetSymbolAddress((void**)&imgf,   g_imgfeat);
    cudaGetSymbolAddress((void**)&finln,  g_finln);
    cudaGetSymbolAddress((void**)&knni,   g_knn_idx);
    cudaGetSymbolAddress((void**)&knnw,   g_knn_w);
    cudaGetSymbolAddress((void**)&wt_ip1, g_wt_ip1);
    cudaGetSymbolAddress((void**)&wt_gd1, g_wt_gd1);
    cudaGetSymbolAddress((void**)&wt_ip2, g_wt_ip2);
    cudaGetSymbolAddress((void**)&wt_g2,  g_wt_g2);
    cudaGetSymbolAddress((void**)&wt_d2,  g_wt_d2);
    cudaGetSymbolAddress((void**)&bpip,   g_bp_ip);
    cudaGetSymbolAddress((void**)&bpgd,   g_bp_gd);

    cudaFuncSetAttribute(mma_gemm<0>, cudaFuncAttributeMaxDynamicSharedMemorySize, SM_GEMM);
    cudaFuncSetAttribute(mma_gemm<1>, cudaFuncAttributeMaxDynamicSharedMemorySize, SM_GEMM);
    cudaFuncSetAttribute(fused_gd2,  cudaFuncAttributeMaxDynamicSharedMemorySize, SM_FUSED);

    // ncu captures 0-based launch index 3 -> keep the img L1 GEMM there.
    prep_weights<<<(PREP_TOTAL + 255) / 256, 256>>>(
        ip_w1, ip_ln_g, g_w1, g_ln_g, d_w1, d_ln_g, ip_w2, g_w2, d_w2);                 // 0
    prep_bias<<<dim3(HDim / 64, 3), 256>>>(
        ip_w1, ip_ln_b, ip_b1, g_w1, g_ln_b, g_b1, d_w1, d_ln_b, d_b1);                 // 1
    ln_img_kernel<<<ROWS_IMG, 256>>>(it, xln);                                          // 2

    // 3: image MLP layer 1 (PROFILED launch)
    mma_gemm<1><<<dim3(HDim / 128, ROWS_IMG / 128), 256, SM_GEMM>>>(
        xln, IDim, wt_ip1, bpip, hbuf, IDim, HDim);

    // 4: image MLP layer 2 -> imgfeat (fp16 plain)
    mma_gemm<0><<<dim3(ODim / 128, ROWS_IMG / 128), 256, SM_GEMM>>>(
        hbuf, HDim, wt_ip2, ip_b2, imgf, HDim, ODim);

    knn_kernel<<<dim3(Bb, Nn / 256), 256>>>(pc, icd, ivm, knni, knnw);                  // 5
    fin_ln_kernel<<<ROWS_PT, 128>>>(pt, pvm, finln);                                    // 6

    // 7: fused gate|delta layer 1 -> hbuf [ROWS_PT, 1024]
    mma_gemm<1><<<dim3((2 * HDim) / 128, ROWS_PT / 128), 256, SM_GEMM>>>(
        finln, 2 * ODim, wt_gd1, bpgd, hbuf, 2 * ODim, 2 * HDim);

    // 8: fused gate-L2 + delta-L2 + combine -> out
    fused_gd2<<<dim3(ODim / 128, ROWS_PT / 128), 256, SM_FUSED>>>(
        hbuf, wt_g2, wt_d2, g_b2, d_b2, pt, pvm, out);
}

// round 15
// speedup vs baseline: 1.1068x; 1.0027x over previous
#include <cuda_runtime.h>
#include <cuda_fp16.h>
#include <math.h>
#include <stdint.h>

// Problem dims (fixed by the dataset)
#define Bb   16
#define Nn   4096
#define Mm   1024
#define IDim 768
#define HDim 512
#define ODim 256
#define ROWS_IMG (Bb*Mm)   // 16384
#define ROWS_PT  (Bb*Nn)   // 65536

// ---------------- scratch (device globals; no allocation allowed) -------------
__device__ __align__(16) __half g_xln[ROWS_IMG * IDim];          // LN img tokens (fp16, permuted)
__device__ __align__(16) __half g_hbuf[ROWS_PT * 2 * HDim];      // hidden (fp16, permuted)
__device__ __align__(16) __half g_imgfeat[ROWS_IMG * ODim];      // image MLP out (fp16 plain)
__device__ __align__(16) __half g_finln[ROWS_PT * (2 * ODim)];   // fin̂ (fp16, permuted)
__device__ int   g_knn_idx[ROWS_PT * 3];
__device__ float g_knn_w[ROWS_PT * 3];
// transposed (LN-folded) weights: [N,K] K-major, fp16, permuted
__device__ __align__(16) __half g_wt_ip1[HDim * IDim];
__device__ __align__(16) __half g_wt_gd1[(2 * HDim) * HDim];     // fused gate|delta layer-1
__device__ __align__(16) __half g_wt_ip2[ODim * HDim];
__device__ __align__(16) __half g_wt_g2[ODim * HDim];
__device__ __align__(16) __half g_wt_d2[ODim * HDim];
__device__ float g_bp_ip[HDim];
__device__ float g_bp_gd[2 * HDim];                              // fused gate|delta bias

// ---------------- helpers ------------------------------------------------------
// 32-wide k permutation: both 16-k steps of a 32-k tile land in one 16B chunk.
__device__ __host__ __forceinline__ int permk(int k) {
    return (k & ~31) | (((k >> 1) & 3) << 3) | (((k >> 4) & 1) << 2)
         | (((k >> 3) & 1) << 1) | (k & 1);
}
__device__ __forceinline__ float gelu_f(float x) {
    return 0.5f * x * (1.0f + erff(x * 0.70710678118654752f));
}
__device__ __forceinline__ float sigmoid_f(float x) {
    return 1.0f / (1.0f + __expf(-x));
}
__device__ __forceinline__ float2 block_reduce2(float s, float ss) {
    __shared__ float sh[64];
    int lane = threadIdx.x & 31, w = threadIdx.x >> 5;
#pragma unroll
    for (int o = 16; o; o >>= 1) {
        s  += __shfl_down_sync(0xffffffffu, s,  o);
        ss += __shfl_down_sync(0xffffffffu, ss, o);
    }
    if (lane == 0) { sh[w] = s; sh[32 + w] = ss; }
    __syncthreads();
    int nw = (blockDim.x + 31) >> 5;
    if (w == 0) {
        s  = (lane < nw) ? sh[lane]      : 0.0f;
        ss = (lane < nw) ? sh[32 + lane] : 0.0f;
#pragma unroll
        for (int o = 16; o; o >>= 1) {
            s  += __shfl_down_sync(0xffffffffu, s,  o);
            ss += __shfl_down_sync(0xffffffffu, ss, o);
        }
        if (lane == 0) { sh[0] = s; sh[32] = ss; }
    }
    __syncthreads();
    return make_float2(sh[0], sh[32]);
}

// ---------------- K0: ALL weight + bias prep in ONE kernel ----------------------
// blocks [0, 5120):   1,310,720 elementwise fold/transpose jobs
// blocks [5120, 5144): 3 x 8 bias-fold blocks (64 n each)
#define PREP_TOTAL  1310720
#define PREP_WBLK   5120
__global__ void prep_all(const float* __restrict__ ip_w1, const float* __restrict__ ip_g,
                         const float* __restrict__ ip_bln, const float* __restrict__ ip_b1,
                         const float* __restrict__ gw1, const float* __restrict__ gg,
                         const float* __restrict__ g_bln, const float* __restrict__ g_b1,
                         const float* __restrict__ dw1, const float* __restrict__ dg,
                         const float* __restrict__ d_bln, const float* __restrict__ d_b1,
                         const float* __restrict__ ip_w2, const float* __restrict__ gw2,
                         const float* __restrict__ dw2) {
    if (blockIdx.x < PREP_WBLK) {
        int idx = blockIdx.x * 256 + threadIdx.x;
        if (idx < 393216) {
            int k = idx / HDim, n = idx % HDim;
            g_wt_ip1[(size_t)n * IDim + permk(k)] = __float2half_rn(ip_g[k] * ip_w1[idx]);
        } else if (idx < 655360) {
            int e = idx - 393216;
            int k = e / HDim, n = e % HDim;
            g_wt_gd1[(size_t)n * HDim + permk(k)] = __float2half_rn(gg[k] * gw1[e]);
        } else if (idx < 917504) {
            int e = idx - 655360;
            int k = e / HDim, n = e % HDim;
            g_wt_gd1[(size_t)(n + HDim) * HDim + permk(k)] = __float2half_rn(dg[k] * dw1[e]);
        } else if (idx < 1048576) {
            int e = idx - 917504;
            int k = e / ODim, n = e % ODim;
            g_wt_ip2[(size_t)n * HDim + permk(k)] = __float2half_rn(ip_w2[e]);
        } else if (idx < 1179648) {
            int e = idx - 1048576;
            int k = e / ODim, n = e % ODim;
            g_wt_g2[(size_t)n * HDim + permk(k)] = __float2half_rn(gw2[e]);
        } else if (idx < PREP_TOTAL) {
            int e = idx - 1179648;
            int k = e / ODim, n = e % ODim;
            g_wt_d2[(size_t)n * HDim + permk(k)] = __float2half_rn(dw2[e]);
        }
        return;
    }
    // bias folds: b1p[n] = b1[n] + sum_k bln[k]*W[k,n]
    __shared__ float sh[256];
    int bb = blockIdx.x - PREP_WBLK;       // 0..23
    int seg = bb >> 3, nblk = bb & 7;
    const float *W, *bln, *b1;
    float* outp;
    int Kd;
    if (seg == 0)      { W = ip_w1; bln = ip_bln; b1 = ip_b1; outp = g_bp_ip;        Kd = IDim; }
    else if (seg == 1) { W = gw1;   bln = g_bln;  b1 = g_b1;  outp = g_bp_gd;        Kd = HDim; }
    else               { W = dw1;   bln = d_bln;  b1 = d_b1;  outp = g_bp_gd + HDim; Kd = HDim; }
    int nl = threadIdx.x & 63, ks = threadIdx.x >> 6;
    int n = nblk * 64 + nl;
    float acc = 0.0f;
    for (int k = ks; k < Kd; k += 4)
        acc += bln[k] * W[(size_t)k * HDim + n];
    sh[threadIdx.x] = acc;
    __syncthreads();
    if (ks == 0)
        outp[n] = b1[n] + sh[nl] + sh[64 + nl] + sh[128 + nl] + sh[192 + nl];
}

// ---------------- K1: LN (normalize only), fp16 permuted store ------------------
__global__ void ln_img_kernel(const float* __restrict__ x, __half* __restrict__ y) {
    int row = blockIdx.x, tid = threadIdx.x;
    const float* xr = x + (size_t)row * IDim;
    float v0 = xr[tid], v1 = xr[tid + 256], v2 = xr[tid + 512];
    float s = v0 + v1 + v2;
    float ss = v0 * v0 + v1 * v1 + v2 * v2;
    float2 r = block_reduce2(s, ss);
    float mean = r.x * (1.0f / 768.0f);
    float var  = fmaxf(r.y * (1.0f / 768.0f) - mean * mean, 0.0f);
    float rstd = rsqrtf(var + 1e-5f);
    __half* yr = y + (size_t)row * IDim;
    yr[permk(tid)]       = __float2half_rn((v0 - mean) * rstd);
    yr[permk(tid + 256)] = __float2half_rn((v1 - mean) * rstd);
    yr[permk(tid + 512)] = __float2half_rn((v2 - mean) * rstd);
}

// ---------------- GEMM core: fp16 m16n8k16 mma.sync -----------------------------
#define KTILE   32
#define ROWB    64                           // bytes/row, XOR swizzle (no pad)
#define TILE_B  (128 * ROWB)                 // 8192 bytes
#define STAGE_B (2 * TILE_B)                 // 16384
#define STAGES  4
#define STAGES_BYTES (STAGES * STAGE_B)      // 65536
#define GSTASH_BYTES (256 * 32 * 4)          // 32768: 32 __half2 per thread
#define SM_GEMM  STAGES_BYTES
#define SM_FUSED (STAGES_BYTES + GSTASH_BYTES)

#define CPA_COMMIT() asm volatile("cp.async.commit_group;" ::: "memory")
#define CPA_WAIT2()  asm volatile("cp.async.wait_group 2;" ::: "memory")

__device__ __forceinline__ uint32_t smem_u32(const void* p) {
    uint32_t a;
    asm("{ .reg .u64 t; cvta.to.shared.u64 t, %1; cvt.u32.u64 %0, t; }" : "=r"(a) : "l"(p));
    return a;
}
__device__ __forceinline__ void cpa16(uint32_t so, const __half* gp) {
    asm volatile("cp.async.cg.shared.global [%0], [%1], 16;" :: "r"(so), "l"(gp));
}

__device__ __forceinline__ void mma_f16(float* d, uint32_t a0, uint32_t a1, uint32_t a2,
                                        uint32_t a3, uint32_t b0, uint32_t b1) {
    asm volatile(
        "mma.sync.aligned.m16n8k16.row.col.f32.f16.f16.f32 "
        "{%0,%1,%2,%3}, {%4,%5,%6,%7}, {%8,%9}, {%0,%1,%2,%3};"
        : "+f"(d[0]), "+f"(d[1]), "+f"(d[2]), "+f"(d[3])
        : "r"(a0), "r"(a1), "r"(a2), "r"(a3), "r"(b0), "r"(b1));
}

// consume one 32-k stage: 12 x LDS.128 + 32 MMAs
__device__ __forceinline__ void consume_stage(const char* smem_stage,
        int a_base, int b_base, float acc[4][4][4]) {
    const char* As = smem_stage + a_base;
    const char* Bs = smem_stage + TILE_B + b_base;
    uint4 af[8], bq[4];
#pragma unroll
    for (int mf = 0; mf < 4; mf++) {
        af[2 * mf]     = *(const uint4*)(As + mf * (16 * ROWB));
        af[2 * mf + 1] = *(const uint4*)(As + mf * (16 * ROWB) + 8 * ROWB);
    }
#pragma unroll
    for (int nf = 0; nf < 4; nf++)
        bq[nf] = *(const uint4*)(Bs + nf * (8 * ROWB));
#pragma unroll
    for (int mf = 0; mf < 4; mf++)
#pragma unroll
        for (int nf = 0; nf < 4; nf++) {
            mma_f16(acc[mf][nf],
                    af[2 * mf].x, af[2 * mf + 1].x, af[2 * mf].y, af[2 * mf + 1].y,
                    bq[nf].x, bq[nf].y);
            mma_f16(acc[mf][nf],
                    af[2 * mf].z, af[2 * mf + 1].z, af[2 * mf].w, af[2 * mf + 1].w,
                    bq[nf].z, bq[nf].w);
        }
}

__device__ __forceinline__ void zero_acc(float acc[4][4][4]) {
#pragma unroll
    for (int mf = 0; mf < 4; mf++)
#pragma unroll
        for (int nf = 0; nf < 4; nf++)
#pragma unroll
            for (int e = 0; e < 4; e++) acc[mf][nf][e] = 0.0f;
}

// 4-stage mainloop, unrolled by 4. Requires NK % 4 == 0.
__device__ __forceinline__ void gemm_mainloop(char* smem, uint32_t sb,
        const __half* Ag, int lda, const __half* Bg, int ldb, int NK,
        int a_base, int b_base, float acc[4][4][4]) {
    zero_acc(acc);
    int t = threadIdx.x;
    int r0 = t >> 2, c0 = t & 3;
    int r1 = (t + 256) >> 2, c1 = (t + 256) & 3;
    uint32_t so0 = (uint32_t)(r0 * ROWB + 16 * (c0 ^ (r0 & 3)));
    uint32_t so1 = (uint32_t)(r1 * ROWB + 16 * (c1 ^ (r1 & 3)));
    size_t gA0 = (size_t)r0 * lda + c0 * 8, gA1 = (size_t)r1 * lda + c1 * 8;
    size_t gB0 = (size_t)r0 * ldb + c0 * 8, gB1 = (size_t)r1 * ldb + c1 * 8;

    const __half* Ap = Ag;
    const __half* Bp = Bg;
#pragma unroll
    for (int p = 0; p < 3; p++) {
        uint32_t sA = sb + p * STAGE_B, sB = sA + TILE_B;
        cpa16(sA + so0, Ap + gA0); cpa16(sA + so1, Ap + gA1);
        cpa16(sB + so0, Bp + gB0); cpa16(sB + so1, Bp + gB1);
        CPA_COMMIT();
        Ap += KTILE; Bp += KTILE;
    }
    for (int kt = 0; kt < NK; kt += 4) {
#pragma unroll
        for (int u = 0; u < 4; u++) {
            CPA_WAIT2();
            __syncthreads();
            if (kt + u + 3 < NK) {
                const int st = (u + 3) & 3;
                uint32_t sA = sb + st * STAGE_B, sB = sA + TILE_B;
                cpa16(sA + so0, Ap + gA0); cpa16(sA + so1, Ap + gA1);
                cpa16(sB + so0, Bp + gB0); cpa16(sB + so1, Bp + gB1);
                Ap += KTILE; Bp += KTILE;
            }
            CPA_COMMIT();
            consume_stage(smem + u * STAGE_B, a_base, b_base, acc);
        }
    }
}

// ---------------- K2: standalone GEMM --------------------------------------------
// ACT: 0 -> fp16 plain store (imgfeat), 1 -> gelu + fp16 permuted store (hbuf)
template <int ACT>
__global__ __launch_bounds__(256, 2)
void mma_gemm(const __half* __restrict__ A, int lda, const __half* __restrict__ Bt,
              const float* __restrict__ bias, __half* __restrict__ C,
              int Kd, int Nc) {
    extern __shared__ char smem[];
    uint32_t sb = smem_u32(smem);
    int tid = threadIdx.x, wid = tid >> 5, lane = tid & 31;
    int wm = wid & 1, wn = wid >> 1;
    int g = lane >> 2, i4 = lane & 3;
    int row0 = blockIdx.y * 128, col0 = blockIdx.x * 128;

    const int sc = 16 * (i4 ^ (g & 3));
    const int a_base = (wm * 64 + g) * ROWB + sc;
    const int b_base = (wn * 32 + g) * ROWB + sc;

    float acc[4][4][4];
    gemm_mainloop(smem, sb, A + (size_t)row0 * lda, lda,
                  Bt + (size_t)col0 * Kd, Kd, Kd / KTILE, a_base, b_base, acc);

#pragma unroll
    for (int mf = 0; mf < 4; mf++) {
        int r_lo = row0 + wm * 64 + mf * 16 + g;
#pragma unroll
        for (int nf = 0; nf < 4; nf++) {
            int col = col0 + wn * 32 + nf * 8 + i4 * 2;
            float b0 = bias[col], b1 = bias[col + 1];
#pragma unroll
            for (int h = 0; h < 2; h++) {
                int row = r_lo + h * 8;
                float v0 = acc[mf][nf][h * 2 + 0] + b0;
                float v1 = acc[mf][nf][h * 2 + 1] + b1;
                __half2 o;
                if (ACT == 1) {
                    o.x = __float2half_rn(gelu_f(v0));
                    o.y = __float2half_rn(gelu_f(v1));
                    *(__half2*)(C + (size_t)row * Nc + permk(col)) = o;
                } else {
                    o.x = __float2half_rn(v0);
                    o.y = __float2half_rn(v1);
                    *(__half2*)(C + (size_t)row * Nc + col) = o;
                }
            }
        }
    }
}

// ---------------- K2b: fused gate-L2 + delta-L2 + combine, UNIFIED pipeline ------
// 32 virtual k-tiles: tiles [0,16) = gate (A cols 0..511 x wt_g2),
// tiles [16,32) = delta (A cols 512..1023 x wt_d2). A offset is continuous
// (tile t at column t*32), so Ap streams straight across; Bp swaps at t=16.
// At the tile-15 consume, stash sigmoid(gate) (registers only) and zero acc —
// the cp.async pipeline never drains.
__global__ __launch_bounds__(256, 2)
void fused_gd2(const __half* __restrict__ hb, const __half* __restrict__ Bg2,
               const __half* __restrict__ Bd2,
               const float* __restrict__ gbias, const float* __restrict__ dbias,
               const float* __restrict__ ptb, const int* __restrict__ pvm,
               float* __restrict__ out) {
    extern __shared__ char smem[];
    uint32_t sb = smem_u32(smem);
    __half2* stash = (__half2*)(smem + STAGES_BYTES);
    int tid = threadIdx.x, wid = tid >> 5, lane = tid & 31;
    int wm = wid & 1, wn = wid >> 1;
    int g = lane >> 2, i4 = lane & 3;
    int row0 = blockIdx.y * 128, col0 = blockIdx.x * 128;

    const int sc = 16 * (i4 ^ (g & 3));
    const int a_base = (wm * 64 + g) * ROWB + sc;
    const int b_base = (wn * 32 + g) * ROWB + sc;
    const int lda = 2 * HDim, ldb = HDim;
    const int NKT = 32;                      // 16 gate + 16 delta

    // per-thread copy offsets
    int t = tid;
    int r0 = t >> 2, c0 = t & 3;
    int r1 = (t + 256) >> 2, c1 = (t + 256) & 3;
    uint32_t so0 = (uint32_t)(r0 * ROWB + 16 * (c0 ^ (r0 & 3)));
    uint32_t so1 = (uint32_t)(r1 * ROWB + 16 * (c1 ^ (r1 & 3)));
    size_t gA0 = (size_t)r0 * lda + c0 * 8, gA1 = (size_t)r1 * lda + c1 * 8;
    size_t gB0 = (size_t)r0 * ldb + c0 * 8, gB1 = (size_t)r1 * ldb + c1 * 8;

    const __half* Ap = hb + (size_t)row0 * lda;          // streams over 32 tiles
    const __half* Bp = Bg2 + (size_t)col0 * ldb;
    const __half* Bd_base = Bd2 + (size_t)col0 * ldb;
    __half2* tst = stash + tid * 32;

    float acc[4][4][4];
    zero_acc(acc);

    int it = 0;   // next tile index to issue
#pragma unroll
    for (int p = 0; p < 3; p++) {
        uint32_t sA = sb + p * STAGE_B, sB = sA + TILE_B;
        cpa16(sA + so0, Ap + gA0); cpa16(sA + so1, Ap + gA1);
        cpa16(sB + so0, Bp + gB0); cpa16(sB + so1, Bp + gB1);
        CPA_COMMIT();
        Ap += KTILE; it++;
        Bp = (it == 16) ? Bd_base : Bp + KTILE;          // (never hits in prologue)
    }

    for (int kt = 0; kt < NKT; kt += 4) {
#pragma unroll
        for (int u = 0; u < 4; u++) {
            CPA_WAIT2();
            __syncthreads();
            if (kt + u + 3 < NKT) {
                const int st = (u + 3) & 3;
                uint32_t sA = sb + st * STAGE_B, sB = sA + TILE_B;
                cpa16(sA + so0, Ap + gA0); cpa16(sA + so1, Ap + gA1);
                cpa16(sB + so0, Bp + gB0); cpa16(sB + so1, Bp + gB1);
                Ap += KTILE; it++;
                Bp = (it == 16) ? Bd_base : Bp + KTILE;
            }
            CPA_COMMIT();
            consume_stage(smem + u * STAGE_B, a_base, b_base, acc);

            if (kt + u == 15) {
                // gate done: stash sigmoid(gate) (register->private smem), restart acc
#pragma unroll
                for (int mf = 0; mf < 4; mf++)
#pragma unroll
                    for (int nf = 0; nf < 4; nf++) {
                        int col = col0 + wn * 32 + nf * 8 + i4 * 2;
                        float b0 = gbias[col], b1 = gbias[col + 1];
#pragma unroll
                        for (int h = 0; h < 2; h++) {
                            __half2 o;
                            o.x = __float2half_rn(sigmoid_f(acc[mf][nf][h * 2 + 0] + b0));
                            o.y = __float2half_rn(sigmoid_f(acc[mf][nf][h * 2 + 1] + b1));
                            tst[(mf * 4 + nf) * 2 + h] = o;
                        }
                    }
                zero_acc(acc);
            }
        }
    }

    // epilogue: out = (pt + gate * delta) * pv
#pragma unroll
    for (int mf = 0; mf < 4; mf++) {
        int r_lo = row0 + wm * 64 + mf * 16 + g;
#pragma unroll
        for (int nf = 0; nf < 4; nf++) {
            int col = col0 + wn * 32 + nf * 8 + i4 * 2;
            float b0 = dbias[col], b1 = dbias[col + 1];
#pragma unroll
            for (int h = 0; h < 2; h++) {
                int row = r_lo + h * 8;
                float v0 = acc[mf][nf][h * 2 + 0] + b0;
                float v1 = acc[mf][nf][h * 2 + 1] + b1;
                __half2 gt = tst[(mf * 4 + nf) * 2 + h];
                size_t off = (size_t)row * ODim + col;
                float2 p4 = *(const float2*)(ptb + off);
                float m = pvm[row] ? 1.0f : 0.0f;
                float o0 = (p4.x + __half2float(gt.x) * v0) * m;
                float o1 = (p4.y + __half2float(gt.y) * v1) * m;
                *(float2*)(out + off) = make_float2(o0, o1);
            }
        }
    }
}

// ---------------- K3: kNN top-3 + inverse-distance weights ----------------------
__global__ __launch_bounds__(256)
void knn_kernel(const float* __restrict__ pc, const float* __restrict__ ic,
                const int* __restrict__ imask,
                int* __restrict__ knn_idx, float* __restrict__ knn_w) {
    __shared__ float4 cs[Mm];
    int b = blockIdx.x;
    const float INFV = __int_as_float(0x7f800000);
    for (int m = threadIdx.x; m < Mm; m += 256) {
        size_t ci = ((size_t)b * Mm + m) * 3;
        float x = ic[ci], y = ic[ci + 1], z = ic[ci + 2];
        float s2 = imask[b * Mm + m] ? (x * x + y * y + z * z) : INFV;
        cs[m] = make_float4(x, y, z, s2);
    }
    __syncthreads();

    int n = blockIdx.y * 256 + threadIdx.x;
    size_t pidx = (size_t)b * Nn + n;
    float qx = pc[pidx * 3], qy = pc[pidx * 3 + 1], qz = pc[pidx * 3 + 2];
    float q2 = qx * qx + qy * qy + qz * qz;

    float d0 = INFV, d1 = INFV, d2v = INFV;
    int j0 = 0, j1 = 0, j2 = 0;
#pragma unroll 4
    for (int m = 0; m < Mm; m++) {
        float4 c = cs[m];
        float d = fmaxf(q2 + c.w - 2.0f * (qx * c.x + qy * c.y + qz * c.z), 0.0f);
        if (d < d2v) {
            if (d < d1) {
                d2v = d1; j2 = j1;
                if (d < d0) { d1 = d0; j1 = j0; d0 = d; j0 = m; }
                else        { d1 = d;  j1 = m; }
            } else { d2v = d; j2 = m; }
        }
    }
    float w0 = 1.0f / fmaxf(sqrtf(d0),  1e-6f);
    float w1 = 1.0f / fmaxf(sqrtf(d1),  1e-6f);
    float w2 = 1.0f / fmaxf(sqrtf(d2v), 1e-6f);
    float inv = 1.0f / fmaxf(w0 + w1 + w2, 1e-6f);
    size_t base = pidx * 3;
    knn_idx[base + 0] = b * Mm + j0;
    knn_idx[base + 1] = b * Mm + j1;
    knn_idx[base + 2] = b * Mm + j2;
    knn_w[base + 0] = w0 * inv;
    knn_w[base + 1] = w1 * inv;
    knn_w[base + 2] = w2 * inv;
}

// ---------------- K4: gather (fp16 imgfeat) + concat + LN, fp16 permuted --------
__global__ __launch_bounds__(128)
void fin_ln_kernel(const float* __restrict__ pt, const int* __restrict__ pvm,
                   __half* __restrict__ out) {
    int p = blockIdx.x, tid = threadIdx.x;
    float4 v;
    if (tid < 64) {
        v = *(const float4*)&pt[(size_t)p * ODim + tid * 4];
    } else {
        int base = p * 3;
        int i0 = g_knn_idx[base], i1 = g_knn_idx[base + 1], i2 = g_knn_idx[base + 2];
        float w0 = g_knn_w[base], w1 = g_knn_w[base + 1], w2 = g_knn_w[base + 2];
        int o = (tid - 64) * 4;
        __half2 a0 = *(const __half2*)&g_imgfeat[(size_t)i0 * ODim + o];
        __half2 a1 = *(const __half2*)&g_imgfeat[(size_t)i0 * ODim + o + 2];
        __half2 b0 = *(const __half2*)&g_imgfeat[(size_t)i1 * ODim + o];
        __half2 b1 = *(const __half2*)&g_imgfeat[(size_t)i1 * ODim + o + 2];
        __half2 c0 = *(const __half2*)&g_imgfeat[(size_t)i2 * ODim + o];
        __half2 c1 = *(const __half2*)&g_imgfeat[(size_t)i2 * ODim + o + 2];
        float pv = pvm[p] ? 1.0f : 0.0f;
        v.x = (w0 * __half2float(a0.x) + w1 * __half2float(b0.x) + w2 * __half2float(c0.x)) * pv;
        v.y = (w0 * __half2float(a0.y) + w1 * __half2float(b0.y) + w2 * __half2float(c0.y)) * pv;
        v.z = (w0 * __half2float(a1.x) + w1 * __half2float(b1.x) + w2 * __half2float(c1.x)) * pv;
        v.w = (w0 * __half2float(a1.y) + w1 * __half2float(b1.y) + w2 * __half2float(c1.y)) * pv;
    }
    float s  = v.x + v.y + v.z + v.w;
    float ss = v.x * v.x + v.y * v.y + v.z * v.z + v.w * v.w;
    float2 r = block_reduce2(s, ss);
    float mean = r.x * (1.0f / 512.0f);
    float var  = fmaxf(r.y * (1.0f / 512.0f) - mean * mean, 0.0f);
    float rstd = rsqrtf(var + 1e-5f);
    __half* orow = out + (size_t)p * 512;
    int c = tid * 4;
    __half2 o01, o23;
    o01.x = __float2half_rn((v.x - mean) * rstd);
    o01.y = __float2half_rn((v.y - mean) * rstd);
    o23.x = __float2half_rn((v.z - mean) * rstd);
    o23.y = __float2half_rn((v.w - mean) * rstd);
    *(__half2*)(orow + permk(c))     = o01;
    *(__half2*)(orow + permk(c + 2)) = o23;
}

// ---------------- launch ---------------------------------------------------------
extern "C" void kernel_launch(void* const* d_in, const int* in_sizes, int n_in,
                              void* d_out, int out_size) {
    const float* pt      = (const float*)d_in[0];
    const float* pc      = (const float*)d_in[1];
    const float* it      = (const float*)d_in[2];
    const float* icd     = (const float*)d_in[3];
    const int*   pvm     = (const int*)d_in[4];
    const int*   ivm     = (const int*)d_in[5];
    const float* ip_ln_g = (const float*)d_in[6];
    const float* ip_ln_b = (const float*)d_in[7];
    const float* ip_w1   = (const float*)d_in[8];
    const float* ip_b1   = (const float*)d_in[9];
    const float* ip_w2   = (const float*)d_in[10];
    const float* ip_b2   = (const float*)d_in[11];
    const float* g_ln_g  = (const float*)d_in[12];
    const float* g_ln_b  = (const float*)d_in[13];
    const float* g_w1    = (const float*)d_in[14];
    const float* g_b1    = (const float*)d_in[15];
    const float* g_w2    = (const float*)d_in[16];
    const float* g_b2    = (const float*)d_in[17];
    const float* d_ln_g  = (const float*)d_in[18];
    const float* d_ln_b  = (const float*)d_in[19];
    const float* d_w1    = (const float*)d_in[20];
    const float* d_b1    = (const float*)d_in[21];
    const float* d_w2    = (const float*)d_in[22];
    const float* d_b2    = (const float*)d_in[23];
    float* out = (float*)d_out;

    __half *xln, *hbuf, *imgf, *finln, *wt_ip1, *wt_gd1, *wt_ip2, *wt_g2, *wt_d2;
    float *knnw, *bpip, *bpgd;
    int* knni;
    cudaGetSymbolAddress((void**)&xln,    g_xln);
    cudaGetSymbolAddress((void**)&hbuf,   g_hbuf);
    cudaGetSymbolAddress((void**)&imgf,   g_imgfeat);
    cudaGetSymbolAddress((void**)&finln,  g_finln);
    cudaGetSymbolAddress((void**)&knni,   g_knn_idx);
    cudaGetSymbolAddress((void**)&knnw,   g_knn_w);
    cudaGetSymbolAddress((void**)&wt_ip1, g_wt_ip1);
    cudaGetSymbolAddress((void**)&wt_gd1, g_wt_gd1);
    cudaGetSymbolAddress((void**)&wt_ip2, g_wt_ip2);
    cudaGetSymbolAddress((void**)&wt_g2,  g_wt_g2);
    cudaGetSymbolAddress((void**)&wt_d2,  g_wt_d2);
    cudaGetSymbolAddress((void**)&bpip,   g_bp_ip);
    cudaGetSymbolAddress((void**)&bpgd,   g_bp_gd);

    cudaFuncSetAttribute(mma_gemm<0>, cudaFuncAttributeMaxDynamicSharedMemorySize, SM_GEMM);
    cudaFuncSetAttribute(mma_gemm<1>, cudaFuncAttributeMaxDynamicSharedMemorySize, SM_GEMM);
    cudaFuncSetAttribute(fused_gd2,  cudaFuncAttributeMaxDynamicSharedMemorySize, SM_FUSED);

    // ncu captures 0-based launch index 3 -> keep the img L1 GEMM there.
    prep_all<<<PREP_WBLK + 24, 256>>>(
        ip_w1, ip_ln_g, ip_ln_b, ip_b1,
        g_w1, g_ln_g, g_ln_b, g_b1,
        d_w1, d_ln_g, d_ln_b, d_b1,
        ip_w2, g_w2, d_w2);                                                             // 0
    ln_img_kernel<<<ROWS_IMG, 256>>>(it, xln);                                          // 1
    knn_kernel<<<dim3(Bb, Nn / 256), 256>>>(pc, icd, ivm, knni, knnw);                  // 2

    // 3: image MLP layer 1 (PROFILED launch)
    mma_gemm<1><<<dim3(HDim / 128, ROWS_IMG / 128), 256, SM_GEMM>>>(
        xln, IDim, wt_ip1, bpip, hbuf, IDim, HDim);

    // 4: image MLP layer 2 -> imgfeat (fp16 plain)
    mma_gemm<0><<<dim3(ODim / 128, ROWS_IMG / 128), 256, SM_GEMM>>>(
        hbuf, HDim, wt_ip2, ip_b2, imgf, HDim, ODim);

    fin_ln_kernel<<<ROWS_PT, 128>>>(pt, pvm, finln);                                    // 5

    // 6: fused gate|delta layer 1 -> hbuf [ROWS_PT, 1024]
    mma_gemm<1><<<dim3((2 * HDim) / 128, ROWS_PT / 128), 256, SM_GEMM>>>(
        finln, 2 * ODim, wt_gd1, bpgd, hbuf, 2 * ODim, 2 * HDim);

    // 7: unified fused gate-L2 + delta-L2 + combine -> out
    fused_gd2<<<dim3(ODim / 128, ROWS_PT / 128), 256, SM_FUSED>>>(
        hbuf, wt_g2, wt_d2, g_b2, d_b2, pt, pvm, out);
}

// round 17
// speedup vs baseline: 1.1108x; 1.0036x over previous
#include <cuda_runtime.h>
#include <cuda_fp16.h>
#include <math.h>
#include <stdint.h>

// Problem dims (fixed by the dataset)
#define Bb   16
#define Nn   4096
#define Mm   1024
#define IDim 768
#define HDim 512
#define ODim 256
#define ROWS_IMG (Bb*Mm)   // 16384
#define ROWS_PT  (Bb*Nn)   // 65536

// ---------------- scratch (device globals; no allocation allowed) -------------
__device__ __align__(16) __half g_xln[ROWS_IMG * IDim];          // LN img tokens (fp16, permuted)
__device__ __align__(16) __half g_hbuf[ROWS_PT * 2 * HDim];      // hidden (fp16, permuted)
__device__ __align__(16) __half g_imgfeat[ROWS_IMG * ODim];      // image MLP out (fp16 plain)
__device__ __align__(16) __half g_finln[ROWS_PT * (2 * ODim)];   // fin̂ (fp16, permuted)
__device__ int   g_knn_idx[ROWS_PT * 3];
__device__ float g_knn_w[ROWS_PT * 3];
// transposed (LN-folded) weights: [N,K] K-major, fp16, permuted
__device__ __align__(16) __half g_wt_ip1[HDim * IDim];
__device__ __align__(16) __half g_wt_gd1[(2 * HDim) * HDim];     // fused gate|delta layer-1
__device__ __align__(16) __half g_wt_ip2[ODim * HDim];
__device__ __align__(16) __half g_wt_g2[ODim * HDim];
__device__ __align__(16) __half g_wt_d2[ODim * HDim];
__device__ float g_bp_ip[HDim];
__device__ float g_bp_gd[2 * HDim];                              // fused gate|delta bias

// ---------------- helpers ------------------------------------------------------
// 32-wide k permutation: both 16-k steps of a 32-k tile land in one 16B chunk.
__device__ __host__ __forceinline__ int permk(int k) {
    return (k & ~31) | (((k >> 1) & 3) << 3) | (((k >> 4) & 1) << 2)
         | (((k >> 3) & 1) << 1) | (k & 1);
}
__device__ __forceinline__ float gelu_f(float x) {
    return 0.5f * x * (1.0f + erff(x * 0.70710678118654752f));
}
__device__ __forceinline__ float sigmoid_f(float x) {
    return 1.0f / (1.0f + __expf(-x));
}
__device__ __forceinline__ float2 block_reduce2(float s, float ss) {
    __shared__ float sh[64];
    int lane = threadIdx.x & 31, w = threadIdx.x >> 5;
#pragma unroll
    for (int o = 16; o; o >>= 1) {
        s  += __shfl_down_sync(0xffffffffu, s,  o);
        ss += __shfl_down_sync(0xffffffffu, ss, o);
    }
    if (lane == 0) { sh[w] = s; sh[32 + w] = ss; }
    __syncthreads();
    int nw = (blockDim.x + 31) >> 5;
    if (w == 0) {
        s  = (lane < nw) ? sh[lane]      : 0.0f;
        ss = (lane < nw) ? sh[32 + lane] : 0.0f;
#pragma unroll
        for (int o = 16; o; o >>= 1) {
            s  += __shfl_down_sync(0xffffffffu, s,  o);
            ss += __shfl_down_sync(0xffffffffu, ss, o);
        }
        if (lane == 0) { sh[0] = s; sh[32] = ss; }
    }
    __syncthreads();
    return make_float2(sh[0], sh[32]);
}

// ---------------- K0: ALL weight + bias prep in ONE kernel ----------------------
#define PREP_TOTAL  1310720
#define PREP_WBLK   5120
__global__ void prep_all(const float* __restrict__ ip_w1, const float* __restrict__ ip_g,
                         const float* __restrict__ ip_bln, const float* __restrict__ ip_b1,
                         const float* __restrict__ gw1, const float* __restrict__ gg,
                         const float* __restrict__ g_bln, const float* __restrict__ g_b1,
                         const float* __restrict__ dw1, const float* __restrict__ dg,
                         const float* __restrict__ d_bln, const float* __restrict__ d_b1,
                         const float* __restrict__ ip_w2, const float* __restrict__ gw2,
                         const float* __restrict__ dw2) {
    if (blockIdx.x < PREP_WBLK) {
        int idx = blockIdx.x * 256 + threadIdx.x;
        if (idx < 393216) {
            int k = idx / HDim, n = idx % HDim;
            g_wt_ip1[(size_t)n * IDim + permk(k)] = __float2half_rn(ip_g[k] * ip_w1[idx]);
        } else if (idx < 655360) {
            int e = idx - 393216;
            int k = e / HDim, n = e % HDim;
            g_wt_gd1[(size_t)n * HDim + permk(k)] = __float2half_rn(gg[k] * gw1[e]);
        } else if (idx < 917504) {
            int e = idx - 655360;
            int k = e / HDim, n = e % HDim;
            g_wt_gd1[(size_t)(n + HDim) * HDim + permk(k)] = __float2half_rn(dg[k] * dw1[e]);
        } else if (idx < 1048576) {
            int e = idx - 917504;
            int k = e / ODim, n = e % ODim;
            g_wt_ip2[(size_t)n * HDim + permk(k)] = __float2half_rn(ip_w2[e]);
        } else if (idx < 1179648) {
            int e = idx - 1048576;
            int k = e / ODim, n = e % ODim;
            g_wt_g2[(size_t)n * HDim + permk(k)] = __float2half_rn(gw2[e]);
        } else if (idx < PREP_TOTAL) {
            int e = idx - 1179648;
            int k = e / ODim, n = e % ODim;
            g_wt_d2[(size_t)n * HDim + permk(k)] = __float2half_rn(dw2[e]);
        }
        return;
    }
    // bias folds: b1p[n] = b1[n] + sum_k bln[k]*W[k,n]
    __shared__ float sh[256];
    int bb = blockIdx.x - PREP_WBLK;       // 0..23
    int seg = bb >> 3, nblk = bb & 7;
    const float *W, *bln, *b1;
    float* outp;
    int Kd;
    if (seg == 0)      { W = ip_w1; bln = ip_bln; b1 = ip_b1; outp = g_bp_ip;        Kd = IDim; }
    else if (seg == 1) { W = gw1;   bln = g_bln;  b1 = g_b1;  outp = g_bp_gd;        Kd = HDim; }
    else               { W = dw1;   bln = d_bln;  b1 = d_b1;  outp = g_bp_gd + HDim; Kd = HDim; }
    int nl = threadIdx.x & 63, ks = threadIdx.x >> 6;
    int n = nblk * 64 + nl;
    float acc = 0.0f;
    for (int k = ks; k < Kd; k += 4)
        acc += bln[k] * W[(size_t)k * HDim + n];
    sh[threadIdx.x] = acc;
    __syncthreads();
    if (ks == 0)
        outp[n] = b1[n] + sh[nl] + sh[64 + nl] + sh[128 + nl] + sh[192 + nl];
}

// ---------------- K1: LN (normalize only), float4 loads, fp16 permuted ----------
__global__ __launch_bounds__(192)
void ln_img_kernel(const float* __restrict__ x, __half* __restrict__ y) {
    int row = blockIdx.x, tid = threadIdx.x;   // 192 threads x float4 = 768 cols
    float4 v = *(const float4*)(x + (size_t)row * IDim + tid * 4);
    float s  = v.x + v.y + v.z + v.w;
    float ss = v.x * v.x + v.y * v.y + v.z * v.z + v.w * v.w;
    float2 r = block_reduce2(s, ss);
    float mean = r.x * (1.0f / 768.0f);
    float var  = fmaxf(r.y * (1.0f / 768.0f) - mean * mean, 0.0f);
    float rstd = rsqrtf(var + 1e-5f);
    __half* yr = y + (size_t)row * IDim;
    int c = tid * 4;
    __half2 o01, o23;
    o01.x = __float2half_rn((v.x - mean) * rstd);
    o01.y = __float2half_rn((v.y - mean) * rstd);
    o23.x = __float2half_rn((v.z - mean) * rstd);
    o23.y = __float2half_rn((v.w - mean) * rstd);
    *(__half2*)(yr + permk(c))     = o01;     // permk(c+1)=permk(c)+1 (pair preserved)
    *(__half2*)(yr + permk(c + 2)) = o23;
}

// ---------------- GEMM core: fp16 m16n8k16 mma.sync -----------------------------
#define KTILE   32
#define ROWB    64                           // bytes/row, XOR swizzle (no pad)
#define TILE_B  (128 * ROWB)                 // 8192 bytes
#define STAGE_B (2 * TILE_B)                 // 16384
#define STAGES  4
#define STAGES_BYTES (STAGES * STAGE_B)      // 65536
#define GSTASH_BYTES (256 * 32 * 4)          // 32768: 32 __half2 per thread
#define SM_GEMM  STAGES_BYTES
#define SM_FUSED (STAGES_BYTES + GSTASH_BYTES)

#define CPA_COMMIT() asm volatile("cp.async.commit_group;" ::: "memory")
#define CPA_WAIT2()  asm volatile("cp.async.wait_group 2;" ::: "memory")

__device__ __forceinline__ uint32_t smem_u32(const void* p) {
    uint32_t a;
    asm("{ .reg .u64 t; cvta.to.shared.u64 t, %1; cvt.u32.u64 %0, t; }" : "=r"(a) : "l"(p));
    return a;
}
__device__ __forceinline__ void cpa16(uint32_t so, const __half* gp) {
    asm volatile("cp.async.cg.shared.global [%0], [%1], 16;" :: "r"(so), "l"(gp));
}

__device__ __forceinline__ void mma_f16(float* d, uint32_t a0, uint32_t a1, uint32_t a2,
                                        uint32_t a3, uint32_t b0, uint32_t b1) {
    asm volatile(
        "mma.sync.aligned.m16n8k16.row.col.f32.f16.f16.f32 "
        "{%0,%1,%2,%3}, {%4,%5,%6,%7}, {%8,%9}, {%0,%1,%2,%3};"
        : "+f"(d[0]), "+f"(d[1]), "+f"(d[2]), "+f"(d[3])
        : "r"(a0), "r"(a1), "r"(a2), "r"(a3), "r"(b0), "r"(b1));
}

// consume one 32-k stage: 12 x LDS.128 + 32 MMAs
__device__ __forceinline__ void consume_stage(const char* smem_stage,
        int a_base, int b_base, float acc[4][4][4]) {
    const char* As = smem_stage + a_base;
    const char* Bs = smem_stage + TILE_B + b_base;
    uint4 af[8], bq[4];
#pragma unroll
    for (int mf = 0; mf < 4; mf++) {
        af[2 * mf]     = *(const uint4*)(As + mf * (16 * ROWB));
        af[2 * mf + 1] = *(const uint4*)(As + mf * (16 * ROWB) + 8 * ROWB);
    }
#pragma unroll
    for (int nf = 0; nf < 4; nf++)
        bq[nf] = *(const uint4*)(Bs + nf * (8 * ROWB));
#pragma unroll
    for (int mf = 0; mf < 4; mf++)
#pragma unroll
        for (int nf = 0; nf < 4; nf++) {
            mma_f16(acc[mf][nf],
                    af[2 * mf].x, af[2 * mf + 1].x, af[2 * mf].y, af[2 * mf + 1].y,
                    bq[nf].x, bq[nf].y);
            mma_f16(acc[mf][nf],
                    af[2 * mf].z, af[2 * mf + 1].z, af[2 * mf].w, af[2 * mf + 1].w,
                    bq[nf].z, bq[nf].w);
        }
}

__device__ __forceinline__ void zero_acc(float acc[4][4][4]) {
#pragma unroll
    for (int mf = 0; mf < 4; mf++)
#pragma unroll
        for (int nf = 0; nf < 4; nf++)
#pragma unroll
            for (int e = 0; e < 4; e++) acc[mf][nf][e] = 0.0f;
}

// 4-stage mainloop, unrolled by 4. Requires NK % 4 == 0.
__device__ __forceinline__ void gemm_mainloop(char* smem, uint32_t sb,
        const __half* Ag, int lda, const __half* Bg, int ldb, int NK,
        int a_base, int b_base, float acc[4][4][4]) {
    zero_acc(acc);
    int t = threadIdx.x;
    int r0 = t >> 2, c0 = t & 3;
    int r1 = (t + 256) >> 2, c1 = (t + 256) & 3;
    uint32_t so0 = (uint32_t)(r0 * ROWB + 16 * (c0 ^ (r0 & 3)));
    uint32_t so1 = (uint32_t)(r1 * ROWB + 16 * (c1 ^ (r1 & 3)));
    size_t gA0 = (size_t)r0 * lda + c0 * 8, gA1 = (size_t)r1 * lda + c1 * 8;
    size_t gB0 = (size_t)r0 * ldb + c0 * 8, gB1 = (size_t)r1 * ldb + c1 * 8;

    const __half* Ap = Ag;
    const __half* Bp = Bg;
#pragma unroll
    for (int p = 0; p < 3; p++) {
        uint32_t sA = sb + p * STAGE_B, sB = sA + TILE_B;
        cpa16(sA + so0, Ap + gA0); cpa16(sA + so1, Ap + gA1);
        cpa16(sB + so0, Bp + gB0); cpa16(sB + so1, Bp + gB1);
        CPA_COMMIT();
        Ap += KTILE; Bp += KTILE;
    }
    for (int kt = 0; kt < NK; kt += 4) {
#pragma unroll
        for (int u = 0; u < 4; u++) {
            CPA_WAIT2();
            __syncthreads();
            if (kt + u + 3 < NK) {
                const int st = (u + 3) & 3;
                uint32_t sA = sb + st * STAGE_B, sB = sA + TILE_B;
                cpa16(sA + so0, Ap + gA0); cpa16(sA + so1, Ap + gA1);
                cpa16(sB + so0, Bp + gB0); cpa16(sB + so1, Bp + gB1);
                Ap += KTILE; Bp += KTILE;
            }
            CPA_COMMIT();
            consume_stage(smem + u * STAGE_B, a_base, b_base, acc);
        }
    }
}

// ---------------- K2: standalone GEMM --------------------------------------------
// ACT: 0 -> fp16 plain store (imgfeat), 1 -> gelu + fp16 permuted store (hbuf)
template <int ACT>
__global__ __launch_bounds__(256, 2)
void mma_gemm(const __half* __restrict__ A, int lda, const __half* __restrict__ Bt,
              const float* __restrict__ bias, __half* __restrict__ C,
              int Kd, int Nc) {
    extern __shared__ char smem[];
    uint32_t sb = smem_u32(smem);
    int tid = threadIdx.x, wid = tid >> 5, lane = tid & 31;
    int wm = wid & 1, wn = wid >> 1;
    int g = lane >> 2, i4 = lane & 3;
    int row0 = blockIdx.y * 128, col0 = blockIdx.x * 128;

    const int sc = 16 * (i4 ^ (g & 3));
    const int a_base = (wm * 64 + g) * ROWB + sc;
    const int b_base = (wn * 32 + g) * ROWB + sc;

    float acc[4][4][4];
    gemm_mainloop(smem, sb, A + (size_t)row0 * lda, lda,
                  Bt + (size_t)col0 * Kd, Kd, Kd / KTILE, a_base, b_base, acc);

#pragma unroll
    for (int mf = 0; mf < 4; mf++) {
        int r_lo = row0 + wm * 64 + mf * 16 + g;
#pragma unroll
        for (int nf = 0; nf < 4; nf++) {
            int col = col0 + wn * 32 + nf * 8 + i4 * 2;
            float b0 = bias[col], b1 = bias[col + 1];
#pragma unroll
            for (int h = 0; h < 2; h++) {
                int row = r_lo + h * 8;
                float v0 = acc[mf][nf][h * 2 + 0] + b0;
                float v1 = acc[mf][nf][h * 2 + 1] + b1;
                __half2 o;
                if (ACT == 1) {
                    o.x = __float2half_rn(gelu_f(v0));
                    o.y = __float2half_rn(gelu_f(v1));
                    *(__half2*)(C + (size_t)row * Nc + permk(col)) = o;
                } else {
                    o.x = __float2half_rn(v0);
                    o.y = __float2half_rn(v1);
                    *(__half2*)(C + (size_t)row * Nc + col) = o;
                }
            }
        }
    }
}

// ---------------- K2b: fused gate-L2 + delta-L2 + combine, UNIFIED pipeline ------
__global__ __launch_bounds__(256, 2)
void fused_gd2(const __half* __restrict__ hb, const __half* __restrict__ Bg2,
               const __half* __restrict__ Bd2,
               const float* __restrict__ gbias, const float* __restrict__ dbias,
               const float* __restrict__ ptb, const int* __restrict__ pvm,
               float* __restrict__ out) {
    extern __shared__ char smem[];
    uint32_t sb = smem_u32(smem);
    __half2* stash = (__half2*)(smem + STAGES_BYTES);
    int tid = threadIdx.x, wid = tid >> 5, lane = tid & 31;
    int wm = wid & 1, wn = wid >> 1;
    int g = lane >> 2, i4 = lane & 3;
    int row0 = blockIdx.y * 128, col0 = blockIdx.x * 128;

    const int sc = 16 * (i4 ^ (g & 3));
    const int a_base = (wm * 64 + g) * ROWB + sc;
    const int b_base = (wn * 32 + g) * ROWB + sc;
    const int lda = 2 * HDim, ldb = HDim;
    const int NKT = 32;                      // 16 gate + 16 delta

    int t = tid;
    int r0 = t >> 2, c0 = t & 3;
    int r1 = (t + 256) >> 2, c1 = (t + 256) & 3;
    uint32_t so0 = (uint32_t)(r0 * ROWB + 16 * (c0 ^ (r0 & 3)));
    uint32_t so1 = (uint32_t)(r1 * ROWB + 16 * (c1 ^ (r1 & 3)));
    size_t gA0 = (size_t)r0 * lda + c0 * 8, gA1 = (size_t)r1 * lda + c1 * 8;
    size_t gB0 = (size_t)r0 * ldb + c0 * 8, gB1 = (size_t)r1 * ldb + c1 * 8;

    const __half* Ap = hb + (size_t)row0 * lda;
    const __half* Bp = Bg2 + (size_t)col0 * ldb;
    const __half* Bd_base = Bd2 + (size_t)col0 * ldb;
    __half2* tst = stash + tid * 32;

    float acc[4][4][4];
    zero_acc(acc);

    int it = 0;
#pragma unroll
    for (int p = 0; p < 3; p++) {
        uint32_t sA = sb + p * STAGE_B, sB = sA + TILE_B;
        cpa16(sA + so0, Ap + gA0); cpa16(sA + so1, Ap + gA1);
        cpa16(sB + so0, Bp + gB0); cpa16(sB + so1, Bp + gB1);
        CPA_COMMIT();
        Ap += KTILE; it++;
        Bp = (it == 16) ? Bd_base : Bp + KTILE;
    }

    for (int kt = 0; kt < NKT; kt += 4) {
#pragma unroll
        for (int u = 0; u < 4; u++) {
            CPA_WAIT2();
            __syncthreads();
            if (kt + u + 3 < NKT) {
                const int st = (u + 3) & 3;
                uint32_t sA = sb + st * STAGE_B, sB = sA + TILE_B;
                cpa16(sA + so0, Ap + gA0); cpa16(sA + so1, Ap + gA1);
                cpa16(sB + so0, Bp + gB0); cpa16(sB + so1, Bp + gB1);
                Ap += KTILE; it++;
                Bp = (it == 16) ? Bd_base : Bp + KTILE;
            }
            CPA_COMMIT();
            consume_stage(smem + u * STAGE_B, a_base, b_base, acc);

            if (kt + u == 15) {
#pragma unroll
                for (int mf = 0; mf < 4; mf++)
#pragma unroll
                    for (int nf = 0; nf < 4; nf++) {
                        int col = col0 + wn * 32 + nf * 8 + i4 * 2;
                        float b0 = gbias[col], b1 = gbias[col + 1];
#pragma unroll
                        for (int h = 0; h < 2; h++) {
                            __half2 o;
                            o.x = __float2half_rn(sigmoid_f(acc[mf][nf][h * 2 + 0] + b0));
                            o.y = __float2half_rn(sigmoid_f(acc[mf][nf][h * 2 + 1] + b1));
                            tst[(mf * 4 + nf) * 2 + h] = o;
                        }
                    }
                zero_acc(acc);
            }
        }
    }

#pragma unroll
    for (int mf = 0; mf < 4; mf++) {
        int r_lo = row0 + wm * 64 + mf * 16 + g;
#pragma unroll
        for (int nf = 0; nf < 4; nf++) {
            int col = col0 + wn * 32 + nf * 8 + i4 * 2;
            float b0 = dbias[col], b1 = dbias[col + 1];
#pragma unroll
            for (int h = 0; h < 2; h++) {
                int row = r_lo + h * 8;
                float v0 = acc[mf][nf][h * 2 + 0] + b0;
                float v1 = acc[mf][nf][h * 2 + 1] + b1;
                __half2 gt = tst[(mf * 4 + nf) * 2 + h];
                size_t off = (size_t)row * ODim + col;
                float2 p4 = *(const float2*)(ptb + off);
                float m = pvm[row] ? 1.0f : 0.0f;
                float o0 = (p4.x + __half2float(gt.x) * v0) * m;
                float o1 = (p4.y + __half2float(gt.y) * v1) * m;
                *(float2*)(out + off) = make_float2(o0, o1);
            }
        }
    }
}

// ---------------- K3: kNN top-3 + inverse-distance weights ----------------------
__global__ __launch_bounds__(256)
void knn_kernel(const float* __restrict__ pc, const float* __restrict__ ic,
                const int* __restrict__ imask,
                int* __restrict__ knn_idx, float* __restrict__ knn_w) {
    __shared__ float4 cs[Mm];
    int b = blockIdx.x;
    const float INFV = __int_as_float(0x7f800000);
    for (int m = threadIdx.x; m < Mm; m += 256) {
        size_t ci = ((size_t)b * Mm + m) * 3;
        float x = ic[ci], y = ic[ci + 1], z = ic[ci + 2];
        float s2 = imask[b * Mm + m] ? (x * x + y * y + z * z) : INFV;
        cs[m] = make_float4(x, y, z, s2);
    }
    __syncthreads();

    int n = blockIdx.y * 256 + threadIdx.x;
    size_t pidx = (size_t)b * Nn + n;
    float qx = pc[pidx * 3], qy = pc[pidx * 3 + 1], qz = pc[pidx * 3 + 2];
    float q2 = qx * qx + qy * qy + qz * qz;

    float d0 = INFV, d1 = INFV, d2v = INFV;
    int j0 = 0, j1 = 0, j2 = 0;
#pragma unroll 4
    for (int m = 0; m < Mm; m++) {
        float4 c = cs[m];
        float d = fmaxf(q2 + c.w - 2.0f * (qx * c.x + qy * c.y + qz * c.z), 0.0f);
        if (d < d2v) {
            if (d < d1) {
                d2v = d1; j2 = j1;
                if (d < d0) { d1 = d0; j1 = j0; d0 = d; j0 = m; }
                else        { d1 = d;  j1 = m; }
            } else { d2v = d; j2 = m; }
        }
    }
    float w0 = 1.0f / fmaxf(sqrtf(d0),  1e-6f);
    float w1 = 1.0f / fmaxf(sqrtf(d1),  1e-6f);
    float w2 = 1.0f / fmaxf(sqrtf(d2v), 1e-6f);
    float inv = 1.0f / fmaxf(w0 + w1 + w2, 1e-6f);
    size_t base = pidx * 3;
    knn_idx[base + 0] = b * Mm + j0;
    knn_idx[base + 1] = b * Mm + j1;
    knn_idx[base + 2] = b * Mm + j2;
    knn_w[base + 0] = w0 * inv;
    knn_w[base + 1] = w1 * inv;
    knn_w[base + 2] = w2 * inv;
}

// ---------------- K4: gather (fp16 imgfeat) + concat + LN, fp16 permuted --------
__global__ __launch_bounds__(128)
void fin_ln_kernel(const float* __restrict__ pt, const int* __restrict__ pvm,
                   __half* __restrict__ out) {
    int p = blockIdx.x, tid = threadIdx.x;
    float4 v;
    if (tid < 64) {
        v = *(const float4*)&pt[(size_t)p * ODim + tid * 4];
    } else {
        int base = p * 3;
        int i0 = g_knn_idx[base], i1 = g_knn_idx[base + 1], i2 = g_knn_idx[base + 2];
        float w0 = g_knn_w[base], w1 = g_knn_w[base + 1], w2 = g_knn_w[base + 2];
        int o = (tid - 64) * 4;
        __half2 a0 = *(const __half2*)&g_imgfeat[(size_t)i0 * ODim + o];
        __half2 a1 = *(const __half2*)&g_imgfeat[(size_t)i0 * ODim + o + 2];
        __half2 b0 = *(const __half2*)&g_imgfeat[(size_t)i1 * ODim + o];
        __half2 b1 = *(const __half2*)&g_imgfeat[(size_t)i1 * ODim + o + 2];
        __half2 c0 = *(const __half2*)&g_imgfeat[(size_t)i2 * ODim + o];
        __half2 c1 = *(const __half2*)&g_imgfeat[(size_t)i2 * ODim + o + 2];
        float pv = pvm[p] ? 1.0f : 0.0f;
        v.x = (w0 * __half2float(a0.x) + w1 * __half2float(b0.x) + w2 * __half2float(c0.x)) * pv;
        v.y = (w0 * __half2float(a0.y) + w1 * __half2float(b0.y) + w2 * __half2float(c0.y)) * pv;
        v.z = (w0 * __half2float(a1.x) + w1 * __half2float(b1.x) + w2 * __half2float(c1.x)) * pv;
        v.w = (w0 * __half2float(a1.y) + w1 * __half2float(b1.y) + w2 * __half2float(c1.y)) * pv;
    }
    float s  = v.x + v.y + v.z + v.w;
    float ss = v.x * v.x + v.y * v.y + v.z * v.z + v.w * v.w;
    float2 r = block_reduce2(s, ss);
    float mean = r.x * (1.0f / 512.0f);
    float var  = fmaxf(r.y * (1.0f / 512.0f) - mean * mean, 0.0f);
    float rstd = rsqrtf(var + 1e-5f);
    __half* orow = out + (size_t)p * 512;
    int c = tid * 4;
    __half2 o01, o23;
    o01.x = __float2half_rn((v.x - mean) * rstd);
    o01.y = __float2half_rn((v.y - mean) * rstd);
    o23.x = __float2half_rn((v.z - mean) * rstd);
    o23.y = __float2half_rn((v.w - mean) * rstd);
    *(__half2*)(orow + permk(c))     = o01;
    *(__half2*)(orow + permk(c + 2)) = o23;
}

// ---------------- launch ---------------------------------------------------------
extern "C" void kernel_launch(void* const* d_in, const int* in_sizes, int n_in,
                              void* d_out, int out_size) {
    const float* pt      = (const float*)d_in[0];
    const float* pc      = (const float*)d_in[1];
    const float* it      = (const float*)d_in[2];
    const float* icd     = (const float*)d_in[3];
    const int*   pvm     = (const int*)d_in[4];
    const int*   ivm     = (const int*)d_in[5];
    const float* ip_ln_g = (const float*)d_in[6];
    const float* ip_ln_b = (const float*)d_in[7];
    const float* ip_w1   = (const float*)d_in[8];
    const float* ip_b1   = (const float*)d_in[9];
    const float* ip_w2   = (const float*)d_in[10];
    const float* ip_b2   = (const float*)d_in[11];
    const float* g_ln_g  = (const float*)d_in[12];
    const float* g_ln_b  = (const float*)d_in[13];
    const float* g_w1    = (const float*)d_in[14];
    const float* g_b1    = (const float*)d_in[15];
    const float* g_w2    = (const float*)d_in[16];
    const float* g_b2    = (const float*)d_in[17];
    const float* d_ln_g  = (const float*)d_in[18];
    const float* d_ln_b  = (const float*)d_in[19];
    const float* d_w1    = (const float*)d_in[20];
    const float* d_b1    = (const float*)d_in[21];
    const float* d_w2    = (const float*)d_in[22];
    const float* d_b2    = (const float*)d_in[23];
    float* out = (float*)d_out;

    __half *xln, *hbuf, *imgf, *finln, *wt_ip1, *wt_gd1, *wt_ip2, *wt_g2, *wt_d2;
    float *knnw, *bpip, *bpgd;
    int* knni;
    cudaGetSymbolAddress((void**)&xln,    g_xln);
    cudaGetSymbolAddress((void**)&hbuf,   g_hbuf);
    cudaGetSymbolAddress((void**)&imgf,   g_imgfeat);
    cudaGetSymbolAddress((void**)&finln,  g_finln);
    cudaGetSymbolAddress((void**)&knni,   g_knn_idx);
    cudaGetSymbolAddress((void**)&knnw,   g_knn_w);
    cudaGetSymbolAddress((void**)&wt_ip1, g_wt_ip1);
    cudaGetSymbolAddress((void**)&wt_gd1, g_wt_gd1);
    cudaGetSymbolAddress((void**)&wt_ip2, g_wt_ip2);
    cudaGetSymbolAddress((void**)&wt_g2,  g_wt_g2);
    cudaGetSymbolAddress((void**)&wt_d2,  g_wt_d2);
    cudaGetSymbolAddress((void**)&bpip,   g_bp_ip);
    cudaGetSymbolAddress((void**)&bpgd,   g_bp_gd);

    cudaFuncSetAttribute(mma_gemm<0>, cudaFuncAttributeMaxDynamicSharedMemorySize, SM_GEMM);
    cudaFuncSetAttribute(mma_gemm<1>, cudaFuncAttributeMaxDynamicSharedMemorySize, SM_GEMM);
    cudaFuncSetAttribute(fused_gd2,  cudaFuncAttributeMaxDynamicSharedMemorySize, SM_FUSED);

    // Single-stream (graph-legal); ncu captures 0-based launch index 3 = img L1 GEMM.
    prep_all<<<PREP_WBLK + 24, 256>>>(
        ip_w1, ip_ln_g, ip_ln_b, ip_b1,
        g_w1, g_ln_g, g_ln_b, g_b1,
        d_w1, d_ln_g, d_ln_b, d_b1,
        ip_w2, g_w2, d_w2);                                                             // 0
    ln_img_kernel<<<ROWS_IMG, 192>>>(it, xln);                                          // 1
    knn_kernel<<<dim3(Bb, Nn / 256), 256>>>(pc, icd, ivm, knni, knnw);                  // 2

    // 3: image MLP layer 1 (PROFILED launch)
    mma_gemm<1><<<dim3(HDim / 128, ROWS_IMG / 128), 256, SM_GEMM>>>(
        xln, IDim, wt_ip1, bpip, hbuf, IDim, HDim);

    // 4: image MLP layer 2 -> imgfeat (fp16 plain)
    mma_gemm<0><<<dim3(ODim / 128, ROWS_IMG / 128), 256, SM_GEMM>>>(
        hbuf, HDim, wt_ip2, ip_b2, imgf, HDim, ODim);

    fin_ln_kernel<<<ROWS_PT, 128>>>(pt, pvm, finln);                                    // 5

    // 6: fused gate|delta layer 1 -> hbuf [ROWS_PT, 1024]
    mma_gemm<1><<<dim3((2 * HDim) / 128, ROWS_PT / 128), 256, SM_GEMM>>>(
        finln, 2 * ODim, wt_gd1, bpgd, hbuf, 2 * ODim, 2 * HDim);

    // 7: unified fused gate-L2 + delta-L2 + combine -> out
    fused_gd2<<<dim3(ODim / 128, ROWS_PT / 128), 256, SM_FUSED>>>(
        hbuf, wt_g2, wt_d2, g_b2, d_b2, pt, pvm, out);
}